// round 5
// baseline (speedup 1.0000x reference)
#include <cuda_runtime.h>

#define EPSF 1e-5f

namespace {
constexpr int NBLK = 1024;
constexpr int THREADS = 512;
constexpr int CTXP = 68;           // pitch%32==4 -> conflict-free frag access
constexpr int WP   = 68;
constexpr int RP   = 68;
constexpr int BP   = 68;
constexpr int PC1  = 132;          // phase-1 pitch (k=128), 132%32==4
constexpr int HS   = 64 * RP + 4;

constexpr int OFF_CTX = 0;                      // 256*68 = 17408
constexpr int OFF_W   = OFF_CTX + 256 * CTXP;   // 4*64*68 = 17408
constexpr int OFF_A   = OFF_W + 4 * 64 * WP;    // 17424
constexpr int OFF_B   = OFF_A + 4 * HS;         // 4352
constexpr int OFF_AB  = OFF_B + 64 * BP;        // 1024
constexpr int SMEM_FLOATS = OFF_AB + 1024;      // 57616 floats = 230464 B
}

__device__ __forceinline__ float warp_sum(float v) {
#pragma unroll
    for (int o = 16; o; o >>= 1) v += __shfl_xor_sync(0xffffffffu, v, o);
    return v;
}
__device__ __forceinline__ unsigned cvt_tf32(float x) {
    unsigned u; asm("cvt.rna.tf32.f32 %0, %1;" : "=r"(u) : "f"(x)); return u;
}
__device__ __forceinline__ float cvtf(float x) { return __uint_as_float(cvt_tf32(x)); }
__device__ __forceinline__ void mma8(float4& c, unsigned a0, unsigned a1, unsigned a2, unsigned a3,
                                     unsigned b0, unsigned b1) {
    asm volatile("mma.sync.aligned.m16n8k8.row.col.f32.tf32.tf32.f32 "
                 "{%0,%1,%2,%3}, {%4,%5,%6,%7}, {%8,%9}, {%0,%1,%2,%3};\n"
                 : "+f"(c.x), "+f"(c.y), "+f"(c.z), "+f"(c.w)
                 : "r"(a0), "r"(a1), "r"(a2), "r"(a3), "r"(b0), "r"(b1));
}
__device__ __forceinline__ unsigned uu(const float* p) { return __float_as_uint(*p); }
__device__ __forceinline__ float dot4(float4 a, float4 b) {
    return fmaf(a.x, b.x, fmaf(a.y, b.y, fmaf(a.z, b.z, a.w * b.w)));
}
__device__ __forceinline__ void fma4(float4& a, float s, float4 w) {
    a.x = fmaf(s, w.x, a.x); a.y = fmaf(s, w.y, a.y);
    a.z = fmaf(s, w.z, a.z); a.w = fmaf(s, w.w, a.w);
}
__device__ __forceinline__ const float4* f4p(const float* p) {
    return reinterpret_cast<const float4*>(p);
}

__global__ __launch_bounds__(THREADS, 1)
void cma_fused(const float* __restrict__ feats, const float* __restrict__ proj_w,
               const float* __restrict__ proj_b, const float* __restrict__ wq,
               const float* __restrict__ wk, const float* __restrict__ wv,
               const float* __restrict__ bq, const float* __restrict__ bk,
               const float* __restrict__ bv, const float* __restrict__ wo,
               const float* __restrict__ bo, const float* __restrict__ ng,
               const float* __restrict__ nb, const float* __restrict__ tfw,
               const float* __restrict__ fg, const float* __restrict__ fb,
               float* __restrict__ out)
{
    (void)bk;  // cancels in the k'-softmax

    extern __shared__ float sm[];
    float* sctx = sm + OFF_CTX;
    float* swgt = sm + OFF_W;
    float* bufA = sm + OFF_A;
    float* bufB = sm + OFF_B;
    float* abuf = sm + OFF_AB;

    const int b    = blockIdx.x;
    const int tid  = threadIdx.x;
    const int lane = tid & 31;
    const int wid  = tid >> 5;    // 0..15
    const int lr   = lane >> 2;   // 0..7
    const int lc   = lane & 3;    // 0..3
    // scalar-phase tiling: 2 rows x 4 cols per thread
    const int r0s  = (tid >> 4) * 2;       // 0..62
    const int c0s  = (tid & 15) * 4;       // 0..60

    float wgt[4];
    {
        float t0 = __ldg(tfw + 0), t1 = __ldg(tfw + 1), t2 = __ldg(tfw + 2), t3 = __ldg(tfw + 3);
        float tm = fmaxf(fmaxf(t0, t1), fmaxf(t2, t3));
        float e0 = __expf(t0 - tm), e1 = __expf(t1 - tm), e2 = __expf(t2 - tm), e3 = __expf(t3 - tm);
        float inv = 1.f / (e0 + e1 + e2 + e3);
        wgt[0] = e0 * inv; wgt[1] = e1 * inv; wgt[2] = e2 * inv; wgt[3] = e3 * inv;
    }

    // ================= Phase 1 (tensor): proj -> sctx[(k*64+d)][t], tf32-rounded =================
    {
        float* spw = bufA;            // A: [d][c] pitch 132
        float* sfT = bufA + 64 * PC1; // B: [t][c] pitch 132
        const int m0 = 16 * (wid & 3);
        const int n0 = 16 * (wid >> 2);
        for (int k = 0; k < 4; k++) {
            const float* fgl = feats + (size_t)(k * NBLK + b) * 8192;
            const float* pwg = proj_w + k * 8192;
#pragma unroll
            for (int idx = tid; idx < 8192; idx += THREADS) {
                int c = idx >> 6, t = idx & 63;
                sfT[t * PC1 + c] = cvtf(fgl[idx]);
            }
#pragma unroll
            for (int idx = tid; idx < 8192; idx += THREADS) {
                int d = idx >> 7, c = idx & 127;
                spw[d * PC1 + c] = cvtf(pwg[idx]);
            }
            __syncthreads();

            float4 acc[2] = {{0,0,0,0},{0,0,0,0}};
            const float* arow = spw + (m0 + lr) * PC1 + lc;
            const float* brow = sfT + (n0 + lr) * PC1 + lc;
#pragma unroll 8
            for (int k0 = 0; k0 < 128; k0 += 8) {
                unsigned a0 = uu(arow + k0),     a1 = uu(arow + 8 * PC1 + k0);
                unsigned a2 = uu(arow + k0 + 4), a3 = uu(arow + 8 * PC1 + k0 + 4);
                mma8(acc[0], a0, a1, a2, a3, uu(brow + k0), uu(brow + k0 + 4));
                mma8(acc[1], a0, a1, a2, a3, uu(brow + 8 * PC1 + k0), uu(brow + 8 * PC1 + k0 + 4));
            }
            float pb0 = __ldg(proj_b + k * 64 + m0 + lr);
            float pb1 = __ldg(proj_b + k * 64 + m0 + lr + 8);
            float* crow0 = sctx + (k * 64 + m0 + lr) * CTXP;
            float* crow1 = crow0 + 8 * CTXP;
#pragma unroll
            for (int j = 0; j < 2; j++) {
                int col = n0 + 8 * j + 2 * lc;
                crow0[col]     = cvtf(acc[j].x + pb0);
                crow0[col + 1] = cvtf(acc[j].y + pb0);
                crow1[col]     = cvtf(acc[j].z + pb1);
                crow1[col + 1] = cvtf(acc[j].w + pb1);
            }
            __syncthreads();
        }
    }

    // ================= Phase 2: per-model attention =================
    for (int i = 0; i < 4; i++) {
        float* swq_ = swgt;                 // [e'][t]
        float* swkT = swgt + 64 * WP;       // [t][e']
        float* swv_ = swgt + 2 * 64 * WP;   // [e][t]
        float* swo_ = swgt + 3 * 64 * WP;   // [e'][e]
        {
            const float* gq = wq + i * 4096; const float* gk = wk + i * 4096;
            const float* gv = wv + i * 4096; const float* go = wo + i * 4096;
#pragma unroll
            for (int idx = tid; idx < 4096; idx += THREADS) {
                int e = idx >> 6, t = idx & 63;
                swq_[e * WP + t] = cvtf(gq[idx]);
                swkT[t * WP + e] = cvtf(gk[idx]);
                swv_[e * WP + t] = cvtf(gv[idx]);
                swo_[e * WP + t] = cvtf(go[idx]);
            }
        }
        __syncthreads();

        // ---- G1 (tensor): QP[r][e'] = bq + q_in[r] @ wq^T -> bufB (m16n16/warp) ----
        {
            const int m0 = 16 * (wid & 3);
            const int n0 = 16 * (wid >> 2);
            int ra = m0 + lr, rb = ra + 8;
            int ja = ((ra >> 4) << 6) + ((ra & 15) << 2) + i;
            int jb = ((rb >> 4) << 6) + ((rb & 15) << 2) + i;
            const float* arow0 = sctx + ja * CTXP + lc;
            const float* arow1 = sctx + jb * CTXP + lc;
            const float* brow  = swq_ + (n0 + lr) * WP + lc;
            float4 acc[2] = {{0,0,0,0},{0,0,0,0}};
#pragma unroll
            for (int k0 = 0; k0 < 64; k0 += 8) {
                unsigned a0 = uu(arow0 + k0), a1 = uu(arow1 + k0);
                unsigned a2 = uu(arow0 + k0 + 4), a3 = uu(arow1 + k0 + 4);
                mma8(acc[0], a0, a1, a2, a3, uu(brow + k0), uu(brow + k0 + 4));
                mma8(acc[1], a0, a1, a2, a3, uu(brow + 8 * WP + k0), uu(brow + 8 * WP + k0 + 4));
            }
            float* crow0 = bufB + (m0 + lr) * BP;
            float* crow1 = crow0 + 8 * BP;
#pragma unroll
            for (int j = 0; j < 2; j++) {
                int col = n0 + 8 * j + 2 * lc;
                float b0 = __ldg(bq + i * 64 + col), b1 = __ldg(bq + i * 64 + col + 1);
                crow0[col]     = cvtf(acc[j].x + b0);
                crow0[col + 1] = cvtf(acc[j].y + b1);
                crow1[col]     = cvtf(acc[j].z + b0);
                crow1[col + 1] = cvtf(acc[j].w + b1);
            }
        }
        __syncthreads();

        // ---- G2 (tensor): QK[h][r][t] = 0.25 * QP[:,head h] @ wkT -> bufA (m16n64/warp per head) ----
        {
            const int h  = wid >> 2;
            const int m0 = 16 * (wid & 3);
            const float* arow = bufB + (m0 + lr) * BP + 16 * h + lc;
            const float* brow = swkT + lr * WP + 16 * h + lc;
            float4 acc[8] = {{0,0,0,0},{0,0,0,0},{0,0,0,0},{0,0,0,0},
                             {0,0,0,0},{0,0,0,0},{0,0,0,0},{0,0,0,0}};
#pragma unroll
            for (int k0 = 0; k0 < 16; k0 += 8) {
                unsigned a0 = uu(arow + k0),     a1 = uu(arow + 8 * BP + k0);
                unsigned a2 = uu(arow + k0 + 4), a3 = uu(arow + 8 * BP + k0 + 4);
#pragma unroll
                for (int j = 0; j < 8; j++) {
                    const float* bp = brow + 8 * j * WP + k0;
                    mma8(acc[j], a0, a1, a2, a3, uu(bp), uu(bp + 4));
                }
            }
            float* crow0 = bufA + h * HS + (m0 + lr) * RP;
            float* crow1 = crow0 + 8 * RP;
#pragma unroll
            for (int j = 0; j < 8; j++) {
                int col = 8 * j + 2 * lc;
                crow0[col]     = cvtf(acc[j].x * 0.25f);
                crow0[col + 1] = cvtf(acc[j].y * 0.25f);
                crow1[col]     = cvtf(acc[j].z * 0.25f);
                crow1[col + 1] = cvtf(acc[j].w * 0.25f);
            }
        }
        __syncthreads();

        // ---- G3a (scalar): scores + softmax over k' -> abuf ----
#pragma unroll
        for (int p = 0; p < 2; p++) {
            int r   = wid * 4 + p * 2 + (lane >> 4);
            int sub = lane & 15;
            int h   = sub >> 2, kp = sub & 3;
            int j   = ((r >> 4) << 6) + ((r & 15) << 2) + kp;
            const float* qr = bufA + h * HS + r * RP;
            const float* cr = sctx + j * CTXP;
            float s = 0.f;
#pragma unroll
            for (int t0 = 0; t0 < 64; t0 += 4) s += dot4(*f4p(qr + t0), *f4p(cr + t0));
            float m = fmaxf(s, __shfl_xor_sync(0xffffffffu, s, 1));
            m = fmaxf(m, __shfl_xor_sync(0xffffffffu, m, 2));
            float pe  = __expf(s - m);
            float den = pe + __shfl_xor_sync(0xffffffffu, pe, 1);
            den += __shfl_xor_sync(0xffffffffu, den, 2);
            abuf[r * 16 + sub] = pe / den;
        }
        __syncthreads();

        // ---- G3b (scalar): AGG[h][r][t] = sum_kp a * ctx (overwrites QK) ----
        {
            int jb_[2];
#pragma unroll
            for (int rr = 0; rr < 2; rr++) {
                int r = r0s + rr;
                jb_[rr] = ((r >> 4) << 6) + ((r & 15) << 2);
            }
#pragma unroll
            for (int h = 0; h < 4; h++) {
                float4 acc[2] = {{0,0,0,0},{0,0,0,0}};
#pragma unroll
                for (int rr = 0; rr < 2; rr++) {
                    float4 a4 = *f4p(abuf + (r0s + rr) * 16 + h * 4);
                    fma4(acc[rr], a4.x, *f4p(sctx + (jb_[rr] + 0) * CTXP + c0s));
                    fma4(acc[rr], a4.y, *f4p(sctx + (jb_[rr] + 1) * CTXP + c0s));
                    fma4(acc[rr], a4.z, *f4p(sctx + (jb_[rr] + 2) * CTXP + c0s));
                    fma4(acc[rr], a4.w, *f4p(sctx + (jb_[rr] + 3) * CTXP + c0s));
                }
#pragma unroll
                for (int rr = 0; rr < 2; rr++) {
                    float* dst = bufA + h * HS + (r0s + rr) * RP + c0s;
                    dst[0] = cvtf(acc[rr].x); dst[1] = cvtf(acc[rr].y);
                    dst[2] = cvtf(acc[rr].z); dst[3] = cvtf(acc[rr].w);
                }
            }
        }
        __syncthreads();

        // ---- G4 (tensor): OA[r][e] = bv + AGG[h(e)] @ wv^T -> bufB (m16n16/warp) ----
        {
            const int m0 = 16 * (wid >> 2);
            const int h  = wid & 3;
            const float* arow = bufA + h * HS + (m0 + lr) * RP + lc;
            const float* brow = swv_ + (16 * h + lr) * WP + lc;
            float4 acc[2] = {{0,0,0,0},{0,0,0,0}};
#pragma unroll
            for (int k0 = 0; k0 < 64; k0 += 8) {
                unsigned a0 = uu(arow + k0),     a1 = uu(arow + 8 * RP + k0);
                unsigned a2 = uu(arow + k0 + 4), a3 = uu(arow + 8 * RP + k0 + 4);
                mma8(acc[0], a0, a1, a2, a3, uu(brow + k0), uu(brow + k0 + 4));
                mma8(acc[1], a0, a1, a2, a3, uu(brow + 8 * WP + k0), uu(brow + 8 * WP + k0 + 4));
            }
            float* crow0 = bufB + (m0 + lr) * BP;
            float* crow1 = crow0 + 8 * BP;
#pragma unroll
            for (int j = 0; j < 2; j++) {
                int col = 16 * h + 8 * j + 2 * lc;
                float b0 = __ldg(bv + i * 64 + col), b1 = __ldg(bv + i * 64 + col + 1);
                crow0[col]     = cvtf(acc[j].x + b0);
                crow0[col + 1] = cvtf(acc[j].y + b1);
                crow1[col]     = cvtf(acc[j].z + b0);
                crow1[col + 1] = cvtf(acc[j].w + b1);
            }
        }
        __syncthreads();

        // ---- G5 (tensor): O[r][e'] = bo + OA @ wo^T -> bufA fp32 (m16n16/warp) ----
        {
            const int m0 = 16 * (wid & 3);
            const int n0 = 16 * (wid >> 2);
            const float* arow = bufB + (m0 + lr) * BP + lc;
            const float* brow = swo_ + (n0 + lr) * WP + lc;
            float4 acc[2] = {{0,0,0,0},{0,0,0,0}};
#pragma unroll
            for (int k0 = 0; k0 < 64; k0 += 8) {
                unsigned a0 = uu(arow + k0),     a1 = uu(arow + 8 * BP + k0);
                unsigned a2 = uu(arow + k0 + 4), a3 = uu(arow + 8 * BP + k0 + 4);
                mma8(acc[0], a0, a1, a2, a3, uu(brow + k0), uu(brow + k0 + 4));
                mma8(acc[1], a0, a1, a2, a3, uu(brow + 8 * WP + k0), uu(brow + 8 * WP + k0 + 4));
            }
            float* crow0 = bufA + (m0 + lr) * RP;
            float* crow1 = crow0 + 8 * RP;
#pragma unroll
            for (int j = 0; j < 2; j++) {
                int col = n0 + 8 * j + 2 * lc;
                float b0 = __ldg(bo + i * 64 + col), b1 = __ldg(bo + i * 64 + col + 1);
                crow0[col]     = acc[j].x + b0;
                crow0[col + 1] = acc[j].y + b1;
                crow1[col]     = acc[j].z + b0;
                crow1[col + 1] = acc[j].w + b1;
            }
        }
        __syncthreads();

        // ---- LN over 64 (+residual q_in), scale by wgt[i], stage into out ----
#pragma unroll
        for (int p = 0; p < 4; p++) {
            int r   = wid * 4 + p;
            int jqr = ((r >> 4) << 6) + ((r & 15) << 2) + i;
            float x0 = bufA[r * RP + lane]      + sctx[jqr * CTXP + lane];
            float x1 = bufA[r * RP + lane + 32] + sctx[jqr * CTXP + lane + 32];
            float mean = warp_sum(x0 + x1) * (1.f / 64.f);
            float d0 = x0 - mean, d1 = x1 - mean;
            float var = warp_sum(d0 * d0 + d1 * d1) * (1.f / 64.f);
            float rs = rsqrtf(var + EPSF);
            float* dst = out + ((size_t)b * 16384 + r * 256 + i * 64);
            dst[lane]      = (d0 * rs * __ldg(ng + i * 64 + lane)      + __ldg(nb + i * 64 + lane))      * wgt[i];
            dst[lane + 32] = (d1 * rs * __ldg(ng + i * 64 + lane + 32) + __ldg(nb + i * 64 + lane + 32)) * wgt[i];
        }
        __syncthreads();
    }

    // ================= Phase 3: final LN over 256, in-place on out =================
    const float4* fg4 = f4p(fg);
    const float4* fb4 = f4p(fb);
#pragma unroll
    for (int p = 0; p < 4; p++) {
        int r = wid * 4 + p;
        float4* row4 = reinterpret_cast<float4*>(out + (size_t)b * 16384 + r * 256);
        float4 xa = row4[lane], xb = row4[lane + 32];
        float s = xa.x + xa.y + xa.z + xa.w + xb.x + xb.y + xb.z + xb.w;
        float mean = warp_sum(s) * (1.f / 256.f);
        xa.x -= mean; xa.y -= mean; xa.z -= mean; xa.w -= mean;
        xb.x -= mean; xb.y -= mean; xb.z -= mean; xb.w -= mean;
        float v = xa.x*xa.x + xa.y*xa.y + xa.z*xa.z + xa.w*xa.w
                + xb.x*xb.x + xb.y*xb.y + xb.z*xb.z + xb.w*xb.w;
        float var = warp_sum(v) * (1.f / 256.f);
        float rs = rsqrtf(var + EPSF);
        float4 ga = fg4[lane], gb = fg4[lane + 32];
        float4 ba = fb4[lane], bb = fb4[lane + 32];
        row4[lane]      = make_float4(fmaf(xa.x * rs, ga.x, ba.x), fmaf(xa.y * rs, ga.y, ba.y),
                                      fmaf(xa.z * rs, ga.z, ba.z), fmaf(xa.w * rs, ga.w, ba.w));
        row4[lane + 32] = make_float4(fmaf(xb.x * rs, gb.x, bb.x), fmaf(xb.y * rs, gb.y, bb.y),
                                      fmaf(xb.z * rs, gb.z, bb.z), fmaf(xb.w * rs, gb.w, bb.w));
    }
}

extern "C" void kernel_launch(void* const* d_in, const int* in_sizes, int n_in,
                              void* d_out, int out_size) {
    (void)in_sizes; (void)n_in; (void)out_size;
    const float* feats  = (const float*)d_in[0];
    const float* proj_w = (const float*)d_in[1];
    const float* proj_b = (const float*)d_in[2];
    const float* wq     = (const float*)d_in[3];
    const float* wk     = (const float*)d_in[4];
    const float* wv     = (const float*)d_in[5];
    const float* bq     = (const float*)d_in[6];
    const float* bk     = (const float*)d_in[7];
    const float* bv     = (const float*)d_in[8];
    const float* wo     = (const float*)d_in[9];
    const float* bo     = (const float*)d_in[10];
    const float* ng     = (const float*)d_in[11];
    const float* nb     = (const float*)d_in[12];
    const float* tfw    = (const float*)d_in[13];
    const float* fg     = (const float*)d_in[14];
    const float* fb     = (const float*)d_in[15];
    float* out = (float*)d_out;

    size_t smem = SMEM_FLOATS * sizeof(float);
    cudaFuncSetAttribute(cma_fused, cudaFuncAttributeMaxDynamicSharedMemorySize, (int)smem);
    cma_fused<<<NBLK, THREADS, smem>>>(feats, proj_w, proj_b, wq, wk, wv, bq, bk, bv,
                                       wo, bo, ng, nb, tfw, fg, fb, out);
}

// round 7
// speedup vs baseline: 1.7153x; 1.7153x over previous
#include <cuda_runtime.h>
#include <cuda_fp16.h>

#define EPSF 1e-5f

namespace {
constexpr int NBLK = 1024;
constexpr int THREADS = 256;
// all units in halves unless noted
constexpr int CTXP = 72;            // 36 words/row, 36%32==4 -> conflict-free frags
constexpr int WP   = 72;
constexpr int BP   = 72;
constexpr int PC1  = 136;           // phase-1 k=128 pitch (68 words, %32==4)
constexpr int HS   = 64 * 72 + 8;   // bufA head stride (4616 h = 2308 w, %32==4)
constexpr int OP   = 66;            // fp32 O-buffer pitch (floats)

constexpr int OFF_CTX = 0;                      // 256*72 = 18432 h
constexpr int OFF_W   = OFF_CTX + 256 * CTXP;   // 2 slots * 64*72 = 9216 h
constexpr int OFF_W1  = OFF_W + 64 * WP;
constexpr int OFF_A   = OFF_W + 2 * 64 * WP;    // 4*HS = 18464 h
constexpr int OFF_B   = OFF_A + 4 * HS;         // 4608 h
constexpr int OFF_AB  = OFF_B + 64 * BP;        // fp32 abuf: 1024 f = 2048 h
constexpr int SMEM_HALVES = OFF_AB + 2048;      // 52768 h = 105536 B  (2 CTA/SM)
}

__device__ __forceinline__ float warp_sum(float v) {
#pragma unroll
    for (int o = 16; o; o >>= 1) v += __shfl_xor_sync(0xffffffffu, v, o);
    return v;
}
__device__ __forceinline__ void mma16(float4& c, unsigned a0, unsigned a1, unsigned a2, unsigned a3,
                                      unsigned b0, unsigned b1) {
    asm volatile("mma.sync.aligned.m16n8k16.row.col.f32.f16.f16.f32 "
                 "{%0,%1,%2,%3}, {%4,%5,%6,%7}, {%8,%9}, {%0,%1,%2,%3};\n"
                 : "+f"(c.x), "+f"(c.y), "+f"(c.z), "+f"(c.w)
                 : "r"(a0), "r"(a1), "r"(a2), "r"(a3), "r"(b0), "r"(b1));
}
__device__ __forceinline__ unsigned u2(const __half* p) {
    return *reinterpret_cast<const unsigned*>(p);
}
__device__ __forceinline__ void sth2(__half* p, float x, float y) {
    *reinterpret_cast<__half2*>(p) = __floats2half2_rn(x, y);
}
__device__ __forceinline__ float2 ldf2(const __half* p) {
    return __half22float2(*reinterpret_cast<const __half2*>(p));
}

__global__ __launch_bounds__(THREADS, 2)
void cma_fused(const float* __restrict__ feats, const float* __restrict__ proj_w,
               const float* __restrict__ proj_b, const float* __restrict__ wq,
               const float* __restrict__ wk, const float* __restrict__ wv,
               const float* __restrict__ bq, const float* __restrict__ bk,
               const float* __restrict__ bv, const float* __restrict__ wo,
               const float* __restrict__ bo, const float* __restrict__ ng,
               const float* __restrict__ nb, const float* __restrict__ tfw,
               const float* __restrict__ fg, const float* __restrict__ fb,
               float* __restrict__ out)
{
    (void)bk;  // cancels in the k'-softmax

    extern __shared__ __half smh[];
    __half* sctx  = smh + OFF_CTX;
    __half* slot0 = smh + OFF_W;
    __half* slot1 = smh + OFF_W1;
    __half* bufA  = smh + OFF_A;
    __half* bufB  = smh + OFF_B;
    float*  abuf  = reinterpret_cast<float*>(smh + OFF_AB);
    float*  obuf  = reinterpret_cast<float*>(smh + OFF_A);   // fp32 O, reuses dead AGG space

    const int b    = blockIdx.x;
    const int tid  = threadIdx.x;
    const int lane = tid & 31;
    const int wid  = tid >> 5;    // 0..7
    const int lg   = lane >> 2;   // 0..7
    const int lt   = lane & 3;    // 0..3
    const int r0s  = (tid >> 4) * 4;
    const int c0s  = (tid & 15) * 4;

    float wgt[4];
    {
        float t0 = __ldg(tfw + 0), t1 = __ldg(tfw + 1), t2 = __ldg(tfw + 2), t3 = __ldg(tfw + 3);
        float tm = fmaxf(fmaxf(t0, t1), fmaxf(t2, t3));
        float e0 = __expf(t0 - tm), e1 = __expf(t1 - tm), e2 = __expf(t2 - tm), e3 = __expf(t3 - tm);
        float inv = 1.f / (e0 + e1 + e2 + e3);
        wgt[0] = e0 * inv; wgt[1] = e1 * inv; wgt[2] = e2 * inv; wgt[3] = e3 * inv;
    }

    // ================= Phase 1: proj -> sctx[(k*64+d)][t] fp16 =================
    {
        __half* spw = bufA;              // A: [d][c] pitch PC1
        __half* sfT = bufA + 64 * PC1;   // B: [t][c] pitch PC1
        const int m0 = 16 * (wid & 3);
        const int n0 = 32 * (wid >> 2);
        for (int k = 0; k < 4; k++) {
            const float* fgl = feats + (size_t)(k * NBLK + b) * 8192;
            const float* pwg = proj_w + k * 8192;
#pragma unroll
            for (int idx = tid; idx < 8192; idx += THREADS) {
                int c = idx >> 6, t = idx & 63;
                sfT[t * PC1 + c] = __float2half_rn(fgl[idx]);
            }
#pragma unroll
            for (int idx = tid; idx < 8192; idx += THREADS) {
                int d = idx >> 7, c = idx & 127;
                spw[d * PC1 + c] = __float2half_rn(pwg[idx]);
            }
            __syncthreads();

            float4 acc[4] = {{0,0,0,0},{0,0,0,0},{0,0,0,0},{0,0,0,0}};
            const __half* arow = spw + (m0 + lg) * PC1 + 2 * lt;
#pragma unroll
            for (int k0 = 0; k0 < 128; k0 += 16) {
                unsigned a0 = u2(arow + k0),     a1 = u2(arow + 8 * PC1 + k0);
                unsigned a2 = u2(arow + k0 + 8), a3 = u2(arow + 8 * PC1 + k0 + 8);
#pragma unroll
                for (int j = 0; j < 4; j++) {
                    const __half* bp = sfT + (n0 + 8 * j + lg) * PC1 + k0 + 2 * lt;
                    mma16(acc[j], a0, a1, a2, a3, u2(bp), u2(bp + 8));
                }
            }
            float pb0 = __ldg(proj_b + k * 64 + m0 + lg);
            float pb1 = __ldg(proj_b + k * 64 + m0 + lg + 8);
            __half* crow0 = sctx + (k * 64 + m0 + lg) * CTXP;
            __half* crow1 = crow0 + 8 * CTXP;
#pragma unroll
            for (int j = 0; j < 4; j++) {
                int col = n0 + 8 * j + 2 * lt;
                sth2(crow0 + col, acc[j].x + pb0, acc[j].y + pb0);
                sth2(crow1 + col, acc[j].z + pb1, acc[j].w + pb1);
            }
            __syncthreads();
        }
    }

    // ================= Phase 2: per-model attention =================
    for (int i = 0; i < 4; i++) {
        {   // stage wq -> slot0 [e'][t], wk^T -> slot1 [t][e']
            const float* gq = wq + i * 4096; const float* gk = wk + i * 4096;
#pragma unroll
            for (int idx = tid; idx < 4096; idx += THREADS) {
                int e = idx >> 6, t = idx & 63;
                slot0[e * WP + t] = __float2half_rn(gq[idx]);
                slot1[t * WP + e] = __float2half_rn(gk[idx]);
            }
        }
        __syncthreads();

        // ---- G1: QP[r][e'] = bq + q_in @ wq^T -> bufB (m16n32/warp) ----
        {
            const int m0 = 16 * (wid & 3);
            const int n0 = 32 * (wid >> 2);
            int ra = m0 + lg, rb = ra + 8;
            int ja = ((ra >> 4) << 6) + ((ra & 15) << 2) + i;
            int jb = ((rb >> 4) << 6) + ((rb & 15) << 2) + i;
            const __half* arow0 = sctx + ja * CTXP + 2 * lt;
            const __half* arow1 = sctx + jb * CTXP + 2 * lt;
            float4 acc[4] = {{0,0,0,0},{0,0,0,0},{0,0,0,0},{0,0,0,0}};
#pragma unroll
            for (int k0 = 0; k0 < 64; k0 += 16) {
                unsigned a0 = u2(arow0 + k0),     a1 = u2(arow1 + k0);
                unsigned a2 = u2(arow0 + k0 + 8), a3 = u2(arow1 + k0 + 8);
#pragma unroll
                for (int j = 0; j < 4; j++) {
                    const __half* bp = slot0 + (n0 + 8 * j + lg) * WP + k0 + 2 * lt;
                    mma16(acc[j], a0, a1, a2, a3, u2(bp), u2(bp + 8));
                }
            }
            __half* crow0 = bufB + (m0 + lg) * BP;
            __half* crow1 = crow0 + 8 * BP;
#pragma unroll
            for (int j = 0; j < 4; j++) {
                int col = n0 + 8 * j + 2 * lt;
                float b0 = __ldg(bq + i * 64 + col), b1 = __ldg(bq + i * 64 + col + 1);
                sth2(crow0 + col, acc[j].x + b0, acc[j].y + b1);
                sth2(crow1 + col, acc[j].z + b0, acc[j].w + b1);
            }
        }
        __syncthreads();

        // ---- G2: QK[h][r][t] = 0.25 * QP[:,head h] @ wkT -> bufA (2 m16-tiles x n64 per warp) ----
        {
            const int h  = wid >> 1;
            const int mq = wid & 1;
#pragma unroll
            for (int mt = 0; mt < 2; mt++) {
                const int m0 = 32 * mq + 16 * mt;
                const __half* arow = bufB + (m0 + lg) * BP + 16 * h + 2 * lt;
                unsigned a0 = u2(arow),     a1 = u2(arow + 8 * BP);
                unsigned a2 = u2(arow + 8), a3 = u2(arow + 8 * BP + 8);
                float4 acc[8] = {{0,0,0,0},{0,0,0,0},{0,0,0,0},{0,0,0,0},
                                 {0,0,0,0},{0,0,0,0},{0,0,0,0},{0,0,0,0}};
#pragma unroll
                for (int j = 0; j < 8; j++) {
                    const __half* bp = slot1 + (8 * j + lg) * WP + 16 * h + 2 * lt;
                    mma16(acc[j], a0, a1, a2, a3, u2(bp), u2(bp + 8));
                }
                __half* crow0 = bufA + h * HS + (m0 + lg) * CTXP;
                __half* crow1 = crow0 + 8 * CTXP;
#pragma unroll
                for (int j = 0; j < 8; j++) {
                    int col = 8 * j + 2 * lt;
                    sth2(crow0 + col, acc[j].x * 0.25f, acc[j].y * 0.25f);
                    sth2(crow1 + col, acc[j].z * 0.25f, acc[j].w * 0.25f);
                }
            }
        }
        __syncthreads();

        // ---- restage wv -> slot0 [e][t], wo -> slot1 [e'][e]; then G3a softmax ----
        {
            const float* gv = wv + i * 4096; const float* go = wo + i * 4096;
#pragma unroll
            for (int idx = tid; idx < 4096; idx += THREADS) {
                int e = idx >> 6, t = idx & 63;
                slot0[e * WP + t] = __float2half_rn(gv[idx]);
                slot1[e * WP + t] = __float2half_rn(go[idx]);
            }
        }
#pragma unroll
        for (int p = 0; p < 4; p++) {
            int r   = wid * 8 + p * 2 + (lane >> 4);
            int sub = lane & 15;
            int h   = sub >> 2, kp = sub & 3;
            int j   = ((r >> 4) << 6) + ((r & 15) << 2) + kp;
            const __half* qr = bufA + h * HS + r * CTXP;
            const __half* cr = sctx + j * CTXP;
            float s = 0.f;
#pragma unroll
            for (int t0 = 0; t0 < 64; t0 += 2) {
                float2 qa = ldf2(qr + t0), ca = ldf2(cr + t0);
                s = fmaf(qa.x, ca.x, fmaf(qa.y, ca.y, s));
            }
            float m = fmaxf(s, __shfl_xor_sync(0xffffffffu, s, 1));
            m = fmaxf(m, __shfl_xor_sync(0xffffffffu, m, 2));
            float pe  = __expf(s - m);
            float den = pe + __shfl_xor_sync(0xffffffffu, pe, 1);
            den += __shfl_xor_sync(0xffffffffu, den, 2);
            abuf[r * 16 + sub] = pe / den;
        }
        __syncthreads();

        // ---- G3b: AGG[h][r][t] = sum_kp a * ctx  (overwrites QK in bufA) ----
        {
            int jb_[4];
#pragma unroll
            for (int rr = 0; rr < 4; rr++) {
                int r = r0s + rr;
                jb_[rr] = ((r >> 4) << 6) + ((r & 15) << 2);
            }
#pragma unroll
            for (int h = 0; h < 4; h++) {
#pragma unroll
                for (int rr = 0; rr < 4; rr++) {
                    const float4 a4 = *reinterpret_cast<const float4*>(abuf + (r0s + rr) * 16 + h * 4);
                    float4 acc = {0,0,0,0};
#pragma unroll
                    for (int kp = 0; kp < 4; kp++) {
                        float a = (&a4.x)[kp];
                        const __half* cr = sctx + (jb_[rr] + kp) * CTXP + c0s;
                        float2 c01 = ldf2(cr), c23 = ldf2(cr + 2);
                        acc.x = fmaf(a, c01.x, acc.x); acc.y = fmaf(a, c01.y, acc.y);
                        acc.z = fmaf(a, c23.x, acc.z); acc.w = fmaf(a, c23.y, acc.w);
                    }
                    __half* dst = bufA + h * HS + (r0s + rr) * CTXP + c0s;
                    sth2(dst, acc.x, acc.y);
                    sth2(dst + 2, acc.z, acc.w);
                }
            }
        }
        __syncthreads();

        // ---- G4: OA[r][e] = bv + AGG[h(e)] @ wv^T -> bufB (2 m16-tiles x n16 per warp) ----
        {
            const int h  = wid >> 1;
            const int mq = wid & 1;
#pragma unroll
            for (int mt = 0; mt < 2; mt++) {
                const int m0 = 32 * mq + 16 * mt;
                const __half* arow = bufA + h * HS + (m0 + lg) * CTXP + 2 * lt;
                float4 acc[2] = {{0,0,0,0},{0,0,0,0}};
#pragma unroll
                for (int k0 = 0; k0 < 64; k0 += 16) {
                    unsigned a0 = u2(arow + k0),     a1 = u2(arow + 8 * CTXP + k0);
                    unsigned a2 = u2(arow + k0 + 8), a3 = u2(arow + 8 * CTXP + k0 + 8);
#pragma unroll
                    for (int j = 0; j < 2; j++) {
                        const __half* bp = slot0 + (16 * h + 8 * j + lg) * WP + k0 + 2 * lt;
                        mma16(acc[j], a0, a1, a2, a3, u2(bp), u2(bp + 8));
                    }
                }
                __half* crow0 = bufB + (m0 + lg) * BP;
                __half* crow1 = crow0 + 8 * BP;
#pragma unroll
                for (int j = 0; j < 2; j++) {
                    int col = 16 * h + 8 * j + 2 * lt;
                    float b0 = __ldg(bv + i * 64 + col), b1 = __ldg(bv + i * 64 + col + 1);
                    sth2(crow0 + col, acc[j].x + b0, acc[j].y + b1);
                    sth2(crow1 + col, acc[j].z + b0, acc[j].w + b1);
                }
            }
        }
        __syncthreads();

        // ---- G5: O[r][e'] = bo + OA @ wo^T -> obuf fp32 (m16n32/warp) ----
        {
            const int m0 = 16 * (wid & 3);
            const int n0 = 32 * (wid >> 2);
            const __half* arow = bufB + (m0 + lg) * BP + 2 * lt;
            float4 acc[4] = {{0,0,0,0},{0,0,0,0},{0,0,0,0},{0,0,0,0}};
#pragma unroll
            for (int k0 = 0; k0 < 64; k0 += 16) {
                unsigned a0 = u2(arow + k0),     a1 = u2(arow + 8 * BP + k0);
                unsigned a2 = u2(arow + k0 + 8), a3 = u2(arow + 8 * BP + k0 + 8);
#pragma unroll
                for (int j = 0; j < 4; j++) {
                    const __half* bp = slot1 + (n0 + 8 * j + lg) * WP + k0 + 2 * lt;
                    mma16(acc[j], a0, a1, a2, a3, u2(bp), u2(bp + 8));
                }
            }
            float* crow0 = obuf + (m0 + lg) * OP;
            float* crow1 = crow0 + 8 * OP;
#pragma unroll
            for (int j = 0; j < 4; j++) {
                int col = n0 + 8 * j + 2 * lt;
                float b0 = __ldg(bo + i * 64 + col), b1 = __ldg(bo + i * 64 + col + 1);
                crow0[col]     = acc[j].x + b0;
                crow0[col + 1] = acc[j].y + b1;
                crow1[col]     = acc[j].z + b0;
                crow1[col + 1] = acc[j].w + b1;
            }
        }
        __syncthreads();

        // ---- LN over 64 (+residual q_in), scale by wgt[i], stage into out ----
#pragma unroll
        for (int p = 0; p < 8; p++) {
            int r   = wid * 8 + p;
            int jqr = ((r >> 4) << 6) + ((r & 15) << 2) + i;
            float x0 = obuf[r * OP + lane]      + __half2float(sctx[jqr * CTXP + lane]);
            float x1 = obuf[r * OP + lane + 32] + __half2float(sctx[jqr * CTXP + lane + 32]);
            float mean = warp_sum(x0 + x1) * (1.f / 64.f);
            float d0 = x0 - mean, d1 = x1 - mean;
            float var = warp_sum(d0 * d0 + d1 * d1) * (1.f / 64.f);
            float rs = rsqrtf(var + EPSF);
            float* dst = out + ((size_t)b * 16384 + r * 256 + i * 64);
            dst[lane]      = (d0 * rs * __ldg(ng + i * 64 + lane)      + __ldg(nb + i * 64 + lane))      * wgt[i];
            dst[lane + 32] = (d1 * rs * __ldg(ng + i * 64 + lane + 32) + __ldg(nb + i * 64 + lane + 32)) * wgt[i];
        }
        __syncthreads();
    }

    // ================= Phase 3: final LN over 256, in-place on out =================
    const float4* fg4 = reinterpret_cast<const float4*>(fg);
    const float4* fb4 = reinterpret_cast<const float4*>(fb);
#pragma unroll
    for (int p = 0; p < 8; p++) {
        int r = wid * 8 + p;
        float4* row4 = reinterpret_cast<float4*>(out + (size_t)b * 16384 + r * 256);
        float4 xa = row4[lane], xb = row4[lane + 32];
        float s = xa.x + xa.y + xa.z + xa.w + xb.x + xb.y + xb.z + xb.w;
        float mean = warp_sum(s) * (1.f / 256.f);
        xa.x -= mean; xa.y -= mean; xa.z -= mean; xa.w -= mean;
        xb.x -= mean; xb.y -= mean; xb.z -= mean; xb.w -= mean;
        float v = xa.x*xa.x + xa.y*xa.y + xa.z*xa.z + xa.w*xa.w
                + xb.x*xb.x + xb.y*xb.y + xb.z*xb.z + xb.w*xb.w;
        float var = warp_sum(v) * (1.f / 256.f);
        float rs = rsqrtf(var + EPSF);
        float4 ga = fg4[lane], gb = fg4[lane + 32];
        float4 ba = fb4[lane], bb = fb4[lane + 32];
        row4[lane]      = make_float4(fmaf(xa.x * rs, ga.x, ba.x), fmaf(xa.y * rs, ga.y, ba.y),
                                      fmaf(xa.z * rs, ga.z, ba.z), fmaf(xa.w * rs, ga.w, ba.w));
        row4[lane + 32] = make_float4(fmaf(xb.x * rs, gb.x, bb.x), fmaf(xb.y * rs, gb.y, bb.y),
                                      fmaf(xb.z * rs, gb.z, bb.z), fmaf(xb.w * rs, gb.w, bb.w));
    }
}

extern "C" void kernel_launch(void* const* d_in, const int* in_sizes, int n_in,
                              void* d_out, int out_size) {
    (void)in_sizes; (void)n_in; (void)out_size;
    const float* feats  = (const float*)d_in[0];
    const float* proj_w = (const float*)d_in[1];
    const float* proj_b = (const float*)d_in[2];
    const float* wq     = (const float*)d_in[3];
    const float* wk     = (const float*)d_in[4];
    const float* wv     = (const float*)d_in[5];
    const float* bq     = (const float*)d_in[6];
    const float* bk     = (const float*)d_in[7];
    const float* bv     = (const float*)d_in[8];
    const float* wo     = (const float*)d_in[9];
    const float* bo     = (const float*)d_in[10];
    const float* ng     = (const float*)d_in[11];
    const float* nb     = (const float*)d_in[12];
    const float* tfw    = (const float*)d_in[13];
    const float* fg     = (const float*)d_in[14];
    const float* fb     = (const float*)d_in[15];
    float* out = (float*)d_out;

    size_t smem = SMEM_HALVES * sizeof(__half);
    cudaFuncSetAttribute(cma_fused, cudaFuncAttributeMaxDynamicSharedMemorySize, (int)smem);
    cma_fused<<<NBLK, THREADS, smem>>>(feats, proj_w, proj_b, wq, wk, wv, bq, bk, bv,
                                       wo, bo, ng, nb, tfw, fg, fb, out);
}

// round 8
// speedup vs baseline: 1.9365x; 1.1290x over previous
#include <cuda_runtime.h>
#include <cuda_fp16.h>

#define EPSF 1e-5f

namespace {
constexpr int NBLK = 1024;
constexpr int THREADS = 256;
// units = halves unless noted
constexpr int CTXP = 72;            // 36 words/row, %32==4 -> conflict-free frags
constexpr int WP   = 72;
constexpr int BP   = 72;
constexpr int PC1  = 136;           // spw pitch (k=128): 68 words, %32==4
constexpr int FP   = 72;            // sfeat [c][t] pitch
constexpr int HS   = 64 * 72 + 8;   // bufA head stride
constexpr int OP   = 66;            // fp32 O-buffer pitch (floats)

constexpr int OFF_CTX = 0;                      // 256*72 = 18432 h
constexpr int OFF_W   = OFF_CTX + 256 * CTXP;   // 2 slots * 64*72 = 9216 h
constexpr int OFF_W1  = OFF_W + 64 * WP;
constexpr int OFF_A   = OFF_W + 2 * 64 * WP;    // 4*HS = 18464 h (spw+sfeat live here in P1)
constexpr int OFF_B   = OFF_A + 4 * HS;         // 4608 h
constexpr int OFF_AB  = OFF_B + 64 * BP;        // fp32 abuf: 1024 f = 2048 h
constexpr int SMEM_HALVES = OFF_AB + 2048;      // 52768 h = 105536 B (2 CTA/SM)
}

// fp16 weight scratch, converted once per launch by prep kernel
__device__ __half g_pw [4 * 64 * 128];   // [k][d][c]
__device__ __half g_wq [4 * 64 * 64];    // [i][e'][t]
__device__ __half g_wkT[4 * 64 * 64];    // [i][t][e]
__device__ __half g_wv [4 * 64 * 64];    // [i][e][t]
__device__ __half g_wo [4 * 64 * 64];    // [i][e'][e]

__global__ void prep_weights(const float* __restrict__ proj_w, const float* __restrict__ wq,
                             const float* __restrict__ wk, const float* __restrict__ wv,
                             const float* __restrict__ wo) {
    int tid = blockIdx.x * blockDim.x + threadIdx.x;
    int stride = gridDim.x * blockDim.x;
    for (int idx = tid; idx < 32768; idx += stride) g_pw[idx] = __float2half_rn(proj_w[idx]);
    for (int idx = tid; idx < 16384; idx += stride) {
        g_wq[idx] = __float2half_rn(wq[idx]);
        g_wv[idx] = __float2half_rn(wv[idx]);
        g_wo[idx] = __float2half_rn(wo[idx]);
        int i = idx >> 12, r = idx & 4095, e = r >> 6, t = r & 63;
        g_wkT[(i << 12) + t * 64 + e] = __float2half_rn(wk[idx]);
    }
}

__device__ __forceinline__ float warp_sum(float v) {
#pragma unroll
    for (int o = 16; o; o >>= 1) v += __shfl_xor_sync(0xffffffffu, v, o);
    return v;
}
__device__ __forceinline__ void mma16(float4& c, unsigned a0, unsigned a1, unsigned a2, unsigned a3,
                                      unsigned b0, unsigned b1) {
    asm volatile("mma.sync.aligned.m16n8k16.row.col.f32.f16.f16.f32 "
                 "{%0,%1,%2,%3}, {%4,%5,%6,%7}, {%8,%9}, {%0,%1,%2,%3};\n"
                 : "+f"(c.x), "+f"(c.y), "+f"(c.z), "+f"(c.w)
                 : "r"(a0), "r"(a1), "r"(a2), "r"(a3), "r"(b0), "r"(b1));
}
__device__ __forceinline__ unsigned u2(const __half* p) {
    return *reinterpret_cast<const unsigned*>(p);
}
__device__ __forceinline__ void sth2(__half* p, float x, float y) {
    *reinterpret_cast<__half2*>(p) = __floats2half2_rn(x, y);
}
__device__ __forceinline__ float2 ldf2(const __half* p) {
    return __half22float2(*reinterpret_cast<const __half2*>(p));
}
__device__ __forceinline__ unsigned sptr(const void* p) {
    return (unsigned)__cvta_generic_to_shared(p);
}
__device__ __forceinline__ void ldsm4(unsigned& r0, unsigned& r1, unsigned& r2, unsigned& r3, unsigned addr) {
    asm volatile("ldmatrix.sync.aligned.m8n8.x4.shared.b16 {%0,%1,%2,%3}, [%4];"
                 : "=r"(r0), "=r"(r1), "=r"(r2), "=r"(r3) : "r"(addr));
}
__device__ __forceinline__ void ldsm4t(unsigned& r0, unsigned& r1, unsigned& r2, unsigned& r3, unsigned addr) {
    asm volatile("ldmatrix.sync.aligned.m8n8.x4.trans.shared.b16 {%0,%1,%2,%3}, [%4];"
                 : "=r"(r0), "=r"(r1), "=r"(r2), "=r"(r3) : "r"(addr));
}

__global__ __launch_bounds__(THREADS, 2)
void cma_fused(const float* __restrict__ feats,
               const float* __restrict__ proj_b, const float* __restrict__ bq,
               const float* __restrict__ bv, const float* __restrict__ bo,
               const float* __restrict__ ng, const float* __restrict__ nb,
               const float* __restrict__ tfw, const float* __restrict__ fg,
               const float* __restrict__ fb, float* __restrict__ out)
{
    extern __shared__ __half smh[];
    __half* sctx  = smh + OFF_CTX;
    __half* slot0 = smh + OFF_W;
    __half* slot1 = smh + OFF_W1;
    __half* bufA  = smh + OFF_A;
    __half* bufB  = smh + OFF_B;
    float*  abuf  = reinterpret_cast<float*>(smh + OFF_AB);
    float*  obuf  = reinterpret_cast<float*>(smh + OFF_A);

    const int b    = blockIdx.x;
    const int tid  = threadIdx.x;
    const int lane = tid & 31;
    const int wid  = tid >> 5;    // 0..7
    const int lg   = lane >> 2;   // 0..7
    const int lt   = lane & 3;    // 0..3
    const int lm   = lane & 15;   // ldmatrix row-within-16
    const int lk8  = (lane >> 4) * 8;
    const int r0s  = (tid >> 4) * 4;
    const int c0s  = (tid & 15) * 4;

    float wgt[4];
    {
        float t0 = __ldg(tfw + 0), t1 = __ldg(tfw + 1), t2 = __ldg(tfw + 2), t3 = __ldg(tfw + 3);
        float tm = fmaxf(fmaxf(t0, t1), fmaxf(t2, t3));
        float e0 = __expf(t0 - tm), e1 = __expf(t1 - tm), e2 = __expf(t2 - tm), e3 = __expf(t3 - tm);
        float inv = 1.f / (e0 + e1 + e2 + e3);
        wgt[0] = e0 * inv; wgt[1] = e1 * inv; wgt[2] = e2 * inv; wgt[3] = e3 * inv;
    }

    // ================= Phase 1: proj -> sctx[(k*64+d)][t] fp16, LDSM frags =================
    {
        __half* spw   = bufA;              // A: [d][c] pitch PC1
        __half* sfeat = bufA + 64 * PC1;   // B: [c][t] = [k][n] pitch FP
        const int m0 = 16 * (wid & 3);
        const int n0 = 32 * (wid >> 2);
        const unsigned aaddr = sptr(spw + (m0 + lm) * PC1 + lk8);
        const unsigned baddr = sptr(sfeat + lm * FP + n0 + lk8);
        for (int k = 0; k < 4; k++) {
            const float2* fgl = reinterpret_cast<const float2*>(feats + (size_t)(k * NBLK + b) * 8192);
#pragma unroll
            for (int idx = tid; idx < 4096; idx += THREADS) {
                int c = idx >> 5, th2 = idx & 31;
                float2 f = fgl[idx];
                reinterpret_cast<__half2*>(sfeat + c * FP)[th2] = __floats2half2_rn(f.x, f.y);
            }
            const uint4* pws = reinterpret_cast<const uint4*>(g_pw + k * 8192);
#pragma unroll
            for (int idx = tid; idx < 1024; idx += THREADS) {
                int d = idx >> 4, q = idx & 15;
                reinterpret_cast<uint4*>(spw + d * PC1)[q] = pws[idx];
            }
            __syncthreads();

            float4 acc[4] = {{0,0,0,0},{0,0,0,0},{0,0,0,0},{0,0,0,0}};
#pragma unroll
            for (int k0 = 0; k0 < 128; k0 += 16) {
                unsigned a0, a1, a2, a3, b0, b1, b2, b3, c0, c1, c2, c3;
                ldsm4(a0, a1, a2, a3, aaddr + k0 * 2);
                ldsm4t(b0, b1, b2, b3, baddr + k0 * (FP * 2));
                ldsm4t(c0, c1, c2, c3, baddr + k0 * (FP * 2) + 32);
                mma16(acc[0], a0, a1, a2, a3, b0, b1);
                mma16(acc[1], a0, a1, a2, a3, b2, b3);
                mma16(acc[2], a0, a1, a2, a3, c0, c1);
                mma16(acc[3], a0, a1, a2, a3, c2, c3);
            }
            float pb0 = __ldg(proj_b + k * 64 + m0 + lg);
            float pb1 = __ldg(proj_b + k * 64 + m0 + lg + 8);
            __half* crow0 = sctx + (k * 64 + m0 + lg) * CTXP;
            __half* crow1 = crow0 + 8 * CTXP;
#pragma unroll
            for (int j = 0; j < 4; j++) {
                int col = n0 + 8 * j + 2 * lt;
                sth2(crow0 + col, acc[j].x + pb0, acc[j].y + pb0);
                sth2(crow1 + col, acc[j].z + pb1, acc[j].w + pb1);
            }
            __syncthreads();
        }
    }

    // ================= Phase 2: per-model attention =================
    for (int i = 0; i < 4; i++) {
        {   // stage wq -> slot0, wkT -> slot1 (uint4 copies, fp16 source)
            const uint4* s0 = reinterpret_cast<const uint4*>(g_wq + i * 4096);
            const uint4* s1 = reinterpret_cast<const uint4*>(g_wkT + i * 4096);
#pragma unroll
            for (int idx = tid; idx < 512; idx += THREADS) {
                int e = idx >> 3, q = idx & 7;
                reinterpret_cast<uint4*>(slot0 + e * WP)[q] = s0[idx];
                reinterpret_cast<uint4*>(slot1 + e * WP)[q] = s1[idx];
            }
        }
        __syncthreads();

        // ---- G1: QP[r][e'] = bq + q_in @ wq^T -> bufB (m16n32/warp) ----
        {
            const int m0 = 16 * (wid & 3);
            const int n0 = 32 * (wid >> 2);
            int ra = m0 + lg, rb = ra + 8;
            int ja = ((ra >> 4) << 6) + ((ra & 15) << 2) + i;
            int jb = ((rb >> 4) << 6) + ((rb & 15) << 2) + i;
            const __half* arow0 = sctx + ja * CTXP + 2 * lt;
            const __half* arow1 = sctx + jb * CTXP + 2 * lt;
            float4 acc[4] = {{0,0,0,0},{0,0,0,0},{0,0,0,0},{0,0,0,0}};
#pragma unroll
            for (int k0 = 0; k0 < 64; k0 += 16) {
                unsigned a0 = u2(arow0 + k0),     a1 = u2(arow1 + k0);
                unsigned a2 = u2(arow0 + k0 + 8), a3 = u2(arow1 + k0 + 8);
#pragma unroll
                for (int j = 0; j < 4; j++) {
                    const __half* bp = slot0 + (n0 + 8 * j + lg) * WP + k0 + 2 * lt;
                    mma16(acc[j], a0, a1, a2, a3, u2(bp), u2(bp + 8));
                }
            }
            __half* crow0 = bufB + (m0 + lg) * BP;
            __half* crow1 = crow0 + 8 * BP;
#pragma unroll
            for (int j = 0; j < 4; j++) {
                int col = n0 + 8 * j + 2 * lt;
                float b0 = __ldg(bq + i * 64 + col), b1 = __ldg(bq + i * 64 + col + 1);
                sth2(crow0 + col, acc[j].x + b0, acc[j].y + b1);
                sth2(crow1 + col, acc[j].z + b0, acc[j].w + b1);
            }
        }
        __syncthreads();

        // ---- G2: QK[h][r][t] = 0.25 * QP[:,head h] @ wkT -> bufA ----
        {
            const int h  = wid >> 1;
            const int mq = wid & 1;
#pragma unroll
            for (int mt = 0; mt < 2; mt++) {
                const int m0 = 32 * mq + 16 * mt;
                const __half* arow = bufB + (m0 + lg) * BP + 16 * h + 2 * lt;
                unsigned a0 = u2(arow),     a1 = u2(arow + 8 * BP);
                unsigned a2 = u2(arow + 8), a3 = u2(arow + 8 * BP + 8);
                float4 acc[8] = {{0,0,0,0},{0,0,0,0},{0,0,0,0},{0,0,0,0},
                                 {0,0,0,0},{0,0,0,0},{0,0,0,0},{0,0,0,0}};
#pragma unroll
                for (int j = 0; j < 8; j++) {
                    const __half* bp = slot1 + (8 * j + lg) * WP + 16 * h + 2 * lt;
                    mma16(acc[j], a0, a1, a2, a3, u2(bp), u2(bp + 8));
                }
                __half* crow0 = bufA + h * HS + (m0 + lg) * CTXP;
                __half* crow1 = crow0 + 8 * CTXP;
#pragma unroll
                for (int j = 0; j < 8; j++) {
                    int col = 8 * j + 2 * lt;
                    sth2(crow0 + col, acc[j].x * 0.25f, acc[j].y * 0.25f);
                    sth2(crow1 + col, acc[j].z * 0.25f, acc[j].w * 0.25f);
                }
            }
        }
        __syncthreads();

        // ---- restage wv -> slot0, wo -> slot1; then G3a softmax ----
        {
            const uint4* s0 = reinterpret_cast<const uint4*>(g_wv + i * 4096);
            const uint4* s1 = reinterpret_cast<const uint4*>(g_wo + i * 4096);
#pragma unroll
            for (int idx = tid; idx < 512; idx += THREADS) {
                int e = idx >> 3, q = idx & 7;
                reinterpret_cast<uint4*>(slot0 + e * WP)[q] = s0[idx];
                reinterpret_cast<uint4*>(slot1 + e * WP)[q] = s1[idx];
            }
        }
#pragma unroll
        for (int p = 0; p < 4; p++) {
            int r   = wid * 8 + p * 2 + (lane >> 4);
            int sub = lane & 15;
            int h   = sub >> 2, kp = sub & 3;
            int j   = ((r >> 4) << 6) + ((r & 15) << 2) + kp;
            const __half* qr = bufA + h * HS + r * CTXP;
            const __half* cr = sctx + j * CTXP;
            float s = 0.f;
#pragma unroll
            for (int t0 = 0; t0 < 64; t0 += 2) {
                float2 qa = ldf2(qr + t0), ca = ldf2(cr + t0);
                s = fmaf(qa.x, ca.x, fmaf(qa.y, ca.y, s));
            }
            float m = fmaxf(s, __shfl_xor_sync(0xffffffffu, s, 1));
            m = fmaxf(m, __shfl_xor_sync(0xffffffffu, m, 2));
            float pe  = __expf(s - m);
            float den = pe + __shfl_xor_sync(0xffffffffu, pe, 1);
            den += __shfl_xor_sync(0xffffffffu, den, 2);
            abuf[r * 16 + sub] = pe / den;
        }
        __syncthreads();

        // ---- G3b: AGG[h][r][t] = sum_kp a * ctx (overwrites QK in bufA) ----
        {
            int jb_[4];
#pragma unroll
            for (int rr = 0; rr < 4; rr++) {
                int r = r0s + rr;
                jb_[rr] = ((r >> 4) << 6) + ((r & 15) << 2);
            }
#pragma unroll
            for (int h = 0; h < 4; h++) {
#pragma unroll
                for (int rr = 0; rr < 4; rr++) {
                    const float4 a4 = *reinterpret_cast<const float4*>(abuf + (r0s + rr) * 16 + h * 4);
                    float4 acc = {0,0,0,0};
#pragma unroll
                    for (int kp = 0; kp < 4; kp++) {
                        float a = (&a4.x)[kp];
                        const __half* cr = sctx + (jb_[rr] + kp) * CTXP + c0s;
                        float2 c01 = ldf2(cr), c23 = ldf2(cr + 2);
                        acc.x = fmaf(a, c01.x, acc.x); acc.y = fmaf(a, c01.y, acc.y);
                        acc.z = fmaf(a, c23.x, acc.z); acc.w = fmaf(a, c23.y, acc.w);
                    }
                    __half* dst = bufA + h * HS + (r0s + rr) * CTXP + c0s;
                    sth2(dst, acc.x, acc.y);
                    sth2(dst + 2, acc.z, acc.w);
                }
            }
        }
        __syncthreads();

        // ---- G4: OA[r][e] = bv + AGG[h(e)] @ wv^T -> bufB ----
        {
            const int h  = wid >> 1;
            const int mq = wid & 1;
#pragma unroll
            for (int mt = 0; mt < 2; mt++) {
                const int m0 = 32 * mq + 16 * mt;
                const __half* arow = bufA + h * HS + (m0 + lg) * CTXP + 2 * lt;
                float4 acc[2] = {{0,0,0,0},{0,0,0,0}};
#pragma unroll
                for (int k0 = 0; k0 < 64; k0 += 16) {
                    unsigned a0 = u2(arow + k0),     a1 = u2(arow + 8 * CTXP + k0);
                    unsigned a2 = u2(arow + k0 + 8), a3 = u2(arow + 8 * CTXP + k0 + 8);
#pragma unroll
                    for (int j = 0; j < 2; j++) {
                        const __half* bp = slot0 + (16 * h + 8 * j + lg) * WP + k0 + 2 * lt;
                        mma16(acc[j], a0, a1, a2, a3, u2(bp), u2(bp + 8));
                    }
                }
                __half* crow0 = bufB + (m0 + lg) * BP;
                __half* crow1 = crow0 + 8 * BP;
#pragma unroll
                for (int j = 0; j < 2; j++) {
                    int col = 16 * h + 8 * j + 2 * lt;
                    float b0 = __ldg(bv + i * 64 + col), b1 = __ldg(bv + i * 64 + col + 1);
                    sth2(crow0 + col, acc[j].x + b0, acc[j].y + b1);
                    sth2(crow1 + col, acc[j].z + b0, acc[j].w + b1);
                }
            }
        }
        __syncthreads();

        // ---- G5: O[r][e'] = bo + OA @ wo^T -> obuf fp32 ----
        {
            const int m0 = 16 * (wid & 3);
            const int n0 = 32 * (wid >> 2);
            const __half* arow = bufB + (m0 + lg) * BP + 2 * lt;
            float4 acc[4] = {{0,0,0,0},{0,0,0,0},{0,0,0,0},{0,0,0,0}};
#pragma unroll
            for (int k0 = 0; k0 < 64; k0 += 16) {
                unsigned a0 = u2(arow + k0),     a1 = u2(arow + 8 * BP + k0);
                unsigned a2 = u2(arow + k0 + 8), a3 = u2(arow + 8 * BP + k0 + 8);
#pragma unroll
                for (int j = 0; j < 4; j++) {
                    const __half* bp = slot1 + (n0 + 8 * j + lg) * WP + k0 + 2 * lt;
                    mma16(acc[j], a0, a1, a2, a3, u2(bp), u2(bp + 8));
                }
            }
            float* crow0 = obuf + (m0 + lg) * OP;
            float* crow1 = crow0 + 8 * OP;
#pragma unroll
            for (int j = 0; j < 4; j++) {
                int col = n0 + 8 * j + 2 * lt;
                float b0 = __ldg(bo + i * 64 + col), b1 = __ldg(bo + i * 64 + col + 1);
                crow0[col]     = acc[j].x + b0;
                crow0[col + 1] = acc[j].y + b1;
                crow1[col]     = acc[j].z + b0;
                crow1[col + 1] = acc[j].w + b1;
            }
        }
        __syncthreads();

        // ---- LN over 64 (+residual q_in), scale by wgt[i], stage into out ----
#pragma unroll
        for (int p = 0; p < 8; p++) {
            int r   = wid * 8 + p;
            int jqr = ((r >> 4) << 6) + ((r & 15) << 2) + i;
            float x0 = obuf[r * OP + lane]      + __half2float(sctx[jqr * CTXP + lane]);
            float x1 = obuf[r * OP + lane + 32] + __half2float(sctx[jqr * CTXP + lane + 32]);
            float mean = warp_sum(x0 + x1) * (1.f / 64.f);
            float d0 = x0 - mean, d1 = x1 - mean;
            float var = warp_sum(d0 * d0 + d1 * d1) * (1.f / 64.f);
            float rs = rsqrtf(var + EPSF);
            float* dst = out + ((size_t)b * 16384 + r * 256 + i * 64);
            dst[lane]      = (d0 * rs * __ldg(ng + i * 64 + lane)      + __ldg(nb + i * 64 + lane))      * wgt[i];
            dst[lane + 32] = (d1 * rs * __ldg(ng + i * 64 + lane + 32) + __ldg(nb + i * 64 + lane + 32)) * wgt[i];
        }
        __syncthreads();
    }

    // ================= Phase 3: final LN over 256, in-place on out =================
    const float4* fg4 = reinterpret_cast<const float4*>(fg);
    const float4* fb4 = reinterpret_cast<const float4*>(fb);
#pragma unroll
    for (int p = 0; p < 8; p++) {
        int r = wid * 8 + p;
        float4* row4 = reinterpret_cast<float4*>(out + (size_t)b * 16384 + r * 256);
        float4 xa = row4[lane], xb = row4[lane + 32];
        float s = xa.x + xa.y + xa.z + xa.w + xb.x + xb.y + xb.z + xb.w;
        float mean = warp_sum(s) * (1.f / 256.f);
        xa.x -= mean; xa.y -= mean; xa.z -= mean; xa.w -= mean;
        xb.x -= mean; xb.y -= mean; xb.z -= mean; xb.w -= mean;
        float v = xa.x*xa.x + xa.y*xa.y + xa.z*xa.z + xa.w*xa.w
                + xb.x*xb.x + xb.y*xb.y + xb.z*xb.z + xb.w*xb.w;
        float var = warp_sum(v) * (1.f / 256.f);
        float rs = rsqrtf(var + EPSF);
        float4 ga = fg4[lane], gb = fg4[lane + 32];
        float4 ba = fb4[lane], bb = fb4[lane + 32];
        row4[lane]      = make_float4(fmaf(xa.x * rs, ga.x, ba.x), fmaf(xa.y * rs, ga.y, ba.y),
                                      fmaf(xa.z * rs, ga.z, ba.z), fmaf(xa.w * rs, ga.w, ba.w));
        row4[lane + 32] = make_float4(fmaf(xb.x * rs, gb.x, bb.x), fmaf(xb.y * rs, gb.y, bb.y),
                                      fmaf(xb.z * rs, gb.z, bb.z), fmaf(xb.w * rs, gb.w, bb.w));
    }
}

extern "C" void kernel_launch(void* const* d_in, const int* in_sizes, int n_in,
                              void* d_out, int out_size) {
    (void)in_sizes; (void)n_in; (void)out_size;
    const float* feats  = (const float*)d_in[0];
    const float* proj_w = (const float*)d_in[1];
    const float* proj_b = (const float*)d_in[2];
    const float* wq     = (const float*)d_in[3];
    const float* wk     = (const float*)d_in[4];
    const float* wv     = (const float*)d_in[5];
    const float* bq     = (const float*)d_in[6];
    const float* bv     = (const float*)d_in[8];
    const float* wo     = (const float*)d_in[9];
    const float* bo     = (const float*)d_in[10];
    const float* ng     = (const float*)d_in[11];
    const float* nb     = (const float*)d_in[12];
    const float* tfw    = (const float*)d_in[13];
    const float* fg     = (const float*)d_in[14];
    const float* fb     = (const float*)d_in[15];
    float* out = (float*)d_out;

    prep_weights<<<64, 256>>>(proj_w, wq, wk, wv, wo);

    size_t smem = SMEM_HALVES * sizeof(__half);
    cudaFuncSetAttribute(cma_fused, cudaFuncAttributeMaxDynamicSharedMemorySize, (int)smem);
    cma_fused<<<NBLK, THREADS, smem>>>(feats, proj_b, bq, bv, bo,
                                       ng, nb, tfw, fg, fb, out);
}

// round 9
// speedup vs baseline: 2.0222x; 1.0443x over previous
#include <cuda_runtime.h>
#include <cuda_fp16.h>

#define EPSF 1e-5f

namespace {
constexpr int NBLK = 1024;
constexpr int THREADS = 256;
// units = halves unless noted
constexpr int CTXP = 72;            // 144B rows, %32==4 words -> conflict-free ldmatrix
constexpr int WP   = 72;
constexpr int BP   = 72;
constexpr int PC1  = 136;           // spw pitch (k=128)
constexpr int FP   = 72;            // sfeat [c][t] pitch
constexpr int HS   = 64 * 72 + 8;   // bufA head stride (9232 B, 16B-aligned)
constexpr int OP   = 66;            // fp32 O-buffer pitch (floats)

constexpr int OFF_CTX = 0;
constexpr int OFF_W   = OFF_CTX + 256 * CTXP;
constexpr int OFF_W1  = OFF_W + 64 * WP;
constexpr int OFF_A   = OFF_W + 2 * 64 * WP;
constexpr int OFF_B   = OFF_A + 4 * HS;
constexpr int OFF_AB  = OFF_B + 64 * BP;
constexpr int SMEM_HALVES = OFF_AB + 2048;      // 105536 B (2 CTA/SM)
}

// fp16 weight scratch, converted once per launch
__device__ __half g_pw [4 * 64 * 128];   // [k][d][c]
__device__ __half g_wq [4 * 64 * 64];    // [i][e'][t]
__device__ __half g_wkT[4 * 64 * 64];    // [i][t][e]
__device__ __half g_wv [4 * 64 * 64];    // [i][e][t]
__device__ __half g_wo [4 * 64 * 64];    // [i][e'][e]

__global__ void prep_weights(const float* __restrict__ proj_w, const float* __restrict__ wq,
                             const float* __restrict__ wk, const float* __restrict__ wv,
                             const float* __restrict__ wo) {
    int tid = blockIdx.x * blockDim.x + threadIdx.x;
    int stride = gridDim.x * blockDim.x;
    for (int idx = tid; idx < 32768; idx += stride) g_pw[idx] = __float2half_rn(proj_w[idx]);
    for (int idx = tid; idx < 16384; idx += stride) {
        g_wq[idx] = __float2half_rn(wq[idx]);
        g_wv[idx] = __float2half_rn(wv[idx]);
        g_wo[idx] = __float2half_rn(wo[idx]);
        int i = idx >> 12, r = idx & 4095, e = r >> 6, t = r & 63;
        g_wkT[(i << 12) + t * 64 + e] = __float2half_rn(wk[idx]);
    }
}

__device__ __forceinline__ float warp_sum(float v) {
#pragma unroll
    for (int o = 16; o; o >>= 1) v += __shfl_xor_sync(0xffffffffu, v, o);
    return v;
}
__device__ __forceinline__ void mma16(float4& c, unsigned a0, unsigned a1, unsigned a2, unsigned a3,
                                      unsigned b0, unsigned b1) {
    asm volatile("mma.sync.aligned.m16n8k16.row.col.f32.f16.f16.f32 "
                 "{%0,%1,%2,%3}, {%4,%5,%6,%7}, {%8,%9}, {%0,%1,%2,%3};\n"
                 : "+f"(c.x), "+f"(c.y), "+f"(c.z), "+f"(c.w)
                 : "r"(a0), "r"(a1), "r"(a2), "r"(a3), "r"(b0), "r"(b1));
}
__device__ __forceinline__ void sth2(__half* p, float x, float y) {
    *reinterpret_cast<__half2*>(p) = __floats2half2_rn(x, y);
}
__device__ __forceinline__ unsigned sptr(const void* p) {
    return (unsigned)__cvta_generic_to_shared(p);
}
__device__ __forceinline__ void ldsm4(unsigned& r0, unsigned& r1, unsigned& r2, unsigned& r3, unsigned addr) {
    asm volatile("ldmatrix.sync.aligned.m8n8.x4.shared.b16 {%0,%1,%2,%3}, [%4];"
                 : "=r"(r0), "=r"(r1), "=r"(r2), "=r"(r3) : "r"(addr));
}
__device__ __forceinline__ void ldsm4t(unsigned& r0, unsigned& r1, unsigned& r2, unsigned& r3, unsigned addr) {
    asm volatile("ldmatrix.sync.aligned.m8n8.x4.trans.shared.b16 {%0,%1,%2,%3}, [%4];"
                 : "=r"(r0), "=r"(r1), "=r"(r2), "=r"(r3) : "r"(addr));
}

__global__ __launch_bounds__(THREADS, 2)
void cma_fused(const float* __restrict__ feats,
               const float* __restrict__ proj_b, const float* __restrict__ bq,
               const float* __restrict__ bv, const float* __restrict__ bo,
               const float* __restrict__ ng, const float* __restrict__ nb,
               const float* __restrict__ tfw, const float* __restrict__ fg,
               const float* __restrict__ fb, float* __restrict__ out)
{
    extern __shared__ __half smh[];
    __half* sctx  = smh + OFF_CTX;
    __half* slot0 = smh + OFF_W;
    __half* slot1 = smh + OFF_W1;
    __half* bufA  = smh + OFF_A;
    __half* bufB  = smh + OFF_B;
    float*  abuf  = reinterpret_cast<float*>(smh + OFF_AB);
    float*  obuf  = reinterpret_cast<float*>(smh + OFF_A);

    const int b    = blockIdx.x;
    const int tid  = threadIdx.x;
    const int lane = tid & 31;
    const int wid  = tid >> 5;    // 0..7
    const int lg   = lane >> 2;   // 0..7
    const int lt   = lane & 3;    // 0..3
    const int lm   = lane & 15;   // ldmatrix row-within-16
    const int lk8  = (lane >> 4) * 8;  // ldmatrix k-phase offset
    const int r0s  = (tid >> 4) * 4;
    const int c0s  = (tid & 15) * 4;

    float wgt[4];
    {
        float t0 = __ldg(tfw + 0), t1 = __ldg(tfw + 1), t2 = __ldg(tfw + 2), t3 = __ldg(tfw + 3);
        float tm = fmaxf(fmaxf(t0, t1), fmaxf(t2, t3));
        float e0 = __expf(t0 - tm), e1 = __expf(t1 - tm), e2 = __expf(t2 - tm), e3 = __expf(t3 - tm);
        float inv = 1.f / (e0 + e1 + e2 + e3);
        wgt[0] = e0 * inv; wgt[1] = e1 * inv; wgt[2] = e2 * inv; wgt[3] = e3 * inv;
    }

    // ================= Phase 1: proj -> sctx[(k*64+d)][t] fp16, LDSM frags =================
    {
        __half* spw   = bufA;              // A: [d][c] pitch PC1
        __half* sfeat = bufA + 64 * PC1;   // B: [c][t] pitch FP
        const int m0 = 16 * (wid & 3);
        const int n0 = 32 * (wid >> 2);
        const unsigned aaddr = sptr(spw + (m0 + lm) * PC1 + lk8);
        const unsigned baddr = sptr(sfeat + lm * FP + n0 + lk8);
        for (int k = 0; k < 4; k++) {
            const float2* fgl = reinterpret_cast<const float2*>(feats + (size_t)(k * NBLK + b) * 8192);
#pragma unroll
            for (int idx = tid; idx < 4096; idx += THREADS) {
                int c = idx >> 5, th2 = idx & 31;
                float2 f = fgl[idx];
                reinterpret_cast<__half2*>(sfeat + c * FP)[th2] = __floats2half2_rn(f.x, f.y);
            }
            const uint4* pws = reinterpret_cast<const uint4*>(g_pw + k * 8192);
#pragma unroll
            for (int idx = tid; idx < 1024; idx += THREADS) {
                int d = idx >> 4, q = idx & 15;
                reinterpret_cast<uint4*>(spw + d * PC1)[q] = pws[idx];
            }
            __syncthreads();

            float4 acc[4] = {{0,0,0,0},{0,0,0,0},{0,0,0,0},{0,0,0,0}};
#pragma unroll
            for (int k0 = 0; k0 < 128; k0 += 16) {
                unsigned a0, a1, a2, a3, b0, b1, b2, b3, c0, c1, c2, c3;
                ldsm4(a0, a1, a2, a3, aaddr + k0 * 2);
                ldsm4t(b0, b1, b2, b3, baddr + k0 * (FP * 2));
                ldsm4t(c0, c1, c2, c3, baddr + k0 * (FP * 2) + 32);
                mma16(acc[0], a0, a1, a2, a3, b0, b1);
                mma16(acc[1], a0, a1, a2, a3, b2, b3);
                mma16(acc[2], a0, a1, a2, a3, c0, c1);
                mma16(acc[3], a0, a1, a2, a3, c2, c3);
            }
            float pb0 = __ldg(proj_b + k * 64 + m0 + lg);
            float pb1 = __ldg(proj_b + k * 64 + m0 + lg + 8);
            __half* crow0 = sctx + (k * 64 + m0 + lg) * CTXP;
            __half* crow1 = crow0 + 8 * CTXP;
#pragma unroll
            for (int j = 0; j < 4; j++) {
                int col = n0 + 8 * j + 2 * lt;
                sth2(crow0 + col, acc[j].x + pb0, acc[j].y + pb0);
                sth2(crow1 + col, acc[j].z + pb1, acc[j].w + pb1);
            }
            __syncthreads();
        }
    }

    // ================= Phase 2: per-model attention =================
    for (int i = 0; i < 4; i++) {
        {   // stage wq -> slot0, wkT -> slot1
            const uint4* s0 = reinterpret_cast<const uint4*>(g_wq + i * 4096);
            const uint4* s1 = reinterpret_cast<const uint4*>(g_wkT + i * 4096);
#pragma unroll
            for (int idx = tid; idx < 512; idx += THREADS) {
                int e = idx >> 3, q = idx & 7;
                reinterpret_cast<uint4*>(slot0 + e * WP)[q] = s0[idx];
                reinterpret_cast<uint4*>(slot1 + e * WP)[q] = s1[idx];
            }
        }
        __syncthreads();

        // ---- G1: QP[r][e'] = bq + q_in @ wq^T -> bufB (m16n32/warp, all-LDSM) ----
        {
            const int m0 = 16 * (wid & 3);
            const int n0 = 32 * (wid >> 2);
            int rA = m0 + lm;
            int jA = ((rA >> 4) << 6) + ((rA & 15) << 2) + i;
            const unsigned aaddr = sptr(sctx + jA * CTXP + lk8);
            const unsigned baddr0 = sptr(slot0 + (n0 + lm) * WP + lk8);
            const unsigned baddr1 = sptr(slot0 + (n0 + 16 + lm) * WP + lk8);
            float4 acc[4] = {{0,0,0,0},{0,0,0,0},{0,0,0,0},{0,0,0,0}};
#pragma unroll
            for (int k0 = 0; k0 < 64; k0 += 16) {
                unsigned a0, a1, a2, a3, p0, p1, p2, p3, q0, q1, q2, q3;
                ldsm4(a0, a1, a2, a3, aaddr + k0 * 2);
                ldsm4(p0, p1, p2, p3, baddr0 + k0 * 2);
                ldsm4(q0, q1, q2, q3, baddr1 + k0 * 2);
                mma16(acc[0], a0, a1, a2, a3, p0, p2);
                mma16(acc[1], a0, a1, a2, a3, p1, p3);
                mma16(acc[2], a0, a1, a2, a3, q0, q2);
                mma16(acc[3], a0, a1, a2, a3, q1, q3);
            }
            __half* crow0 = bufB + (m0 + lg) * BP;
            __half* crow1 = crow0 + 8 * BP;
#pragma unroll
            for (int j = 0; j < 4; j++) {
                int col = n0 + 8 * j + 2 * lt;
                float b0 = __ldg(bq + i * 64 + col), b1 = __ldg(bq + i * 64 + col + 1);
                sth2(crow0 + col, acc[j].x + b0, acc[j].y + b1);
                sth2(crow1 + col, acc[j].z + b0, acc[j].w + b1);
            }
        }
        __syncthreads();

        // ---- G2: QK[h][r][t] = 0.25 * QP[:,head h] @ wkT -> bufA (all-LDSM, k=16) ----
        {
            const int h  = wid >> 1;
            const int mq = wid & 1;
#pragma unroll
            for (int mt = 0; mt < 2; mt++) {
                const int m0 = 32 * mq + 16 * mt;
                unsigned a0, a1, a2, a3;
                ldsm4(a0, a1, a2, a3, sptr(bufB + (m0 + lm) * BP + 16 * h + lk8));
                float4 acc[8] = {{0,0,0,0},{0,0,0,0},{0,0,0,0},{0,0,0,0},
                                 {0,0,0,0},{0,0,0,0},{0,0,0,0},{0,0,0,0}};
#pragma unroll
                for (int jj = 0; jj < 4; jj++) {
                    unsigned p0, p1, p2, p3;
                    ldsm4(p0, p1, p2, p3, sptr(slot1 + (16 * jj + lm) * WP + 16 * h + lk8));
                    mma16(acc[2 * jj],     a0, a1, a2, a3, p0, p2);
                    mma16(acc[2 * jj + 1], a0, a1, a2, a3, p1, p3);
                }
                __half* crow0 = bufA + h * HS + (m0 + lg) * CTXP;
                __half* crow1 = crow0 + 8 * CTXP;
#pragma unroll
                for (int j = 0; j < 8; j++) {
                    int col = 8 * j + 2 * lt;
                    sth2(crow0 + col, acc[j].x * 0.25f, acc[j].y * 0.25f);
                    sth2(crow1 + col, acc[j].z * 0.25f, acc[j].w * 0.25f);
                }
            }
        }
        __syncthreads();

        // ---- restage wv -> slot0, wo -> slot1; then G3a softmax (half2 math) ----
        {
            const uint4* s0 = reinterpret_cast<const uint4*>(g_wv + i * 4096);
            const uint4* s1 = reinterpret_cast<const uint4*>(g_wo + i * 4096);
#pragma unroll
            for (int idx = tid; idx < 512; idx += THREADS) {
                int e = idx >> 3, q = idx & 7;
                reinterpret_cast<uint4*>(slot0 + e * WP)[q] = s0[idx];
                reinterpret_cast<uint4*>(slot1 + e * WP)[q] = s1[idx];
            }
        }
#pragma unroll
        for (int p = 0; p < 4; p++) {
            int r   = wid * 8 + p * 2 + (lane >> 4);
            int sub = lane & 15;
            int h   = sub >> 2, kp = sub & 3;
            int j   = ((r >> 4) << 6) + ((r & 15) << 2) + kp;
            const __half2* qr2 = reinterpret_cast<const __half2*>(bufA + h * HS + r * CTXP);
            const __half2* cr2 = reinterpret_cast<const __half2*>(sctx + j * CTXP);
            __half2 ac0 = __float2half2_rn(0.f), ac1 = ac0, ac2 = ac0, ac3 = ac0;
#pragma unroll
            for (int t0 = 0; t0 < 32; t0 += 4) {
                ac0 = __hfma2(qr2[t0],     cr2[t0],     ac0);
                ac1 = __hfma2(qr2[t0 + 1], cr2[t0 + 1], ac1);
                ac2 = __hfma2(qr2[t0 + 2], cr2[t0 + 2], ac2);
                ac3 = __hfma2(qr2[t0 + 3], cr2[t0 + 3], ac3);
            }
            float2 f0 = __half22float2(ac0), f1 = __half22float2(ac1);
            float2 f2 = __half22float2(ac2), f3 = __half22float2(ac3);
            float s = (f0.x + f0.y) + (f1.x + f1.y) + (f2.x + f2.y) + (f3.x + f3.y);
            float m = fmaxf(s, __shfl_xor_sync(0xffffffffu, s, 1));
            m = fmaxf(m, __shfl_xor_sync(0xffffffffu, m, 2));
            float pe  = __expf(s - m);
            float den = pe + __shfl_xor_sync(0xffffffffu, pe, 1);
            den += __shfl_xor_sync(0xffffffffu, den, 2);
            abuf[r * 16 + sub] = pe / den;
        }
        __syncthreads();

        // ---- G3b: AGG[h][r][t] = sum_kp a * ctx (half2 math, overwrites QK) ----
        {
            int jb_[4];
#pragma unroll
            for (int rr = 0; rr < 4; rr++) {
                int r = r0s + rr;
                jb_[rr] = ((r >> 4) << 6) + ((r & 15) << 2);
            }
#pragma unroll
            for (int h = 0; h < 4; h++) {
#pragma unroll
                for (int rr = 0; rr < 4; rr++) {
                    const float4 a4 = *reinterpret_cast<const float4*>(abuf + (r0s + rr) * 16 + h * 4);
                    __half2 acc0 = __float2half2_rn(0.f), acc1 = acc0;
#pragma unroll
                    for (int kp = 0; kp < 4; kp++) {
                        __half2 ah = __float2half2_rn((&a4.x)[kp]);
                        const __half2* cr = reinterpret_cast<const __half2*>(sctx + (jb_[rr] + kp) * CTXP + c0s);
                        acc0 = __hfma2(ah, cr[0], acc0);
                        acc1 = __hfma2(ah, cr[1], acc1);
                    }
                    __half2* dst = reinterpret_cast<__half2*>(bufA + h * HS + (r0s + rr) * CTXP + c0s);
                    dst[0] = acc0;
                    dst[1] = acc1;
                }
            }
        }
        __syncthreads();

        // ---- G4: OA[r][e] = bv + AGG[h(e)] @ wv^T -> bufB (all-LDSM) ----
        {
            const int h  = wid >> 1;
            const int mq = wid & 1;
            const unsigned baddr = sptr(slot0 + (16 * h + lm) * WP + lk8);
#pragma unroll
            for (int mt = 0; mt < 2; mt++) {
                const int m0 = 32 * mq + 16 * mt;
                const unsigned aaddr = sptr(bufA + h * HS + (m0 + lm) * CTXP + lk8);
                float4 acc[2] = {{0,0,0,0},{0,0,0,0}};
#pragma unroll
                for (int k0 = 0; k0 < 64; k0 += 16) {
                    unsigned a0, a1, a2, a3, p0, p1, p2, p3;
                    ldsm4(a0, a1, a2, a3, aaddr + k0 * 2);
                    ldsm4(p0, p1, p2, p3, baddr + k0 * 2);
                    mma16(acc[0], a0, a1, a2, a3, p0, p2);
                    mma16(acc[1], a0, a1, a2, a3, p1, p3);
                }
                __half* crow0 = bufB + (m0 + lg) * BP;
                __half* crow1 = crow0 + 8 * BP;
#pragma unroll
                for (int j = 0; j < 2; j++) {
                    int col = 16 * h + 8 * j + 2 * lt;
                    float b0 = __ldg(bv + i * 64 + col), b1 = __ldg(bv + i * 64 + col + 1);
                    sth2(crow0 + col, acc[j].x + b0, acc[j].y + b1);
                    sth2(crow1 + col, acc[j].z + b0, acc[j].w + b1);
                }
            }
        }
        __syncthreads();

        // ---- G5: O[r][e'] = bo + OA @ wo^T -> obuf fp32 (all-LDSM) ----
        {
            const int m0 = 16 * (wid & 3);
            const int n0 = 32 * (wid >> 2);
            const unsigned aaddr  = sptr(bufB + (m0 + lm) * BP + lk8);
            const unsigned baddr0 = sptr(slot1 + (n0 + lm) * WP + lk8);
            const unsigned baddr1 = sptr(slot1 + (n0 + 16 + lm) * WP + lk8);
            float4 acc[4] = {{0,0,0,0},{0,0,0,0},{0,0,0,0},{0,0,0,0}};
#pragma unroll
            for (int k0 = 0; k0 < 64; k0 += 16) {
                unsigned a0, a1, a2, a3, p0, p1, p2, p3, q0, q1, q2, q3;
                ldsm4(a0, a1, a2, a3, aaddr + k0 * 2);
                ldsm4(p0, p1, p2, p3, baddr0 + k0 * 2);
                ldsm4(q0, q1, q2, q3, baddr1 + k0 * 2);
                mma16(acc[0], a0, a1, a2, a3, p0, p2);
                mma16(acc[1], a0, a1, a2, a3, p1, p3);
                mma16(acc[2], a0, a1, a2, a3, q0, q2);
                mma16(acc[3], a0, a1, a2, a3, q1, q3);
            }
            float* crow0 = obuf + (m0 + lg) * OP;
            float* crow1 = crow0 + 8 * OP;
#pragma unroll
            for (int j = 0; j < 4; j++) {
                int col = n0 + 8 * j + 2 * lt;
                float b0 = __ldg(bo + i * 64 + col), b1 = __ldg(bo + i * 64 + col + 1);
                crow0[col]     = acc[j].x + b0;
                crow0[col + 1] = acc[j].y + b1;
                crow1[col]     = acc[j].z + b0;
                crow1[col + 1] = acc[j].w + b1;
            }
        }
        __syncthreads();

        // ---- LN over 64 (+residual q_in), scale by wgt[i], stage into out ----
#pragma unroll
        for (int p = 0; p < 8; p++) {
            int r   = wid * 8 + p;
            int jqr = ((r >> 4) << 6) + ((r & 15) << 2) + i;
            float x0 = obuf[r * OP + lane]      + __half2float(sctx[jqr * CTXP + lane]);
            float x1 = obuf[r * OP + lane + 32] + __half2float(sctx[jqr * CTXP + lane + 32]);
            float mean = warp_sum(x0 + x1) * (1.f / 64.f);
            float d0 = x0 - mean, d1 = x1 - mean;
            float var = warp_sum(d0 * d0 + d1 * d1) * (1.f / 64.f);
            float rs = rsqrtf(var + EPSF);
            float* dst = out + ((size_t)b * 16384 + r * 256 + i * 64);
            dst[lane]      = (d0 * rs * __ldg(ng + i * 64 + lane)      + __ldg(nb + i * 64 + lane))      * wgt[i];
            dst[lane + 32] = (d1 * rs * __ldg(ng + i * 64 + lane + 32) + __ldg(nb + i * 64 + lane + 32)) * wgt[i];
        }
        __syncthreads();
    }

    // ================= Phase 3: final LN over 256, in-place on out =================
    const float4* fg4 = reinterpret_cast<const float4*>(fg);
    const float4* fb4 = reinterpret_cast<const float4*>(fb);
#pragma unroll
    for (int p = 0; p < 8; p++) {
        int r = wid * 8 + p;
        float4* row4 = reinterpret_cast<float4*>(out + (size_t)b * 16384 + r * 256);
        float4 xa = row4[lane], xb = row4[lane + 32];
        float s = xa.x + xa.y + xa.z + xa.w + xb.x + xb.y + xb.z + xb.w;
        float mean = warp_sum(s) * (1.f / 256.f);
        xa.x -= mean; xa.y -= mean; xa.z -= mean; xa.w -= mean;
        xb.x -= mean; xb.y -= mean; xb.z -= mean; xb.w -= mean;
        float v = xa.x*xa.x + xa.y*xa.y + xa.z*xa.z + xa.w*xa.w
                + xb.x*xb.x + xb.y*xb.y + xb.z*xb.z + xb.w*xb.w;
        float var = warp_sum(v) * (1.f / 256.f);
        float rs = rsqrtf(var + EPSF);
        float4 ga = fg4[lane], gb = fg4[lane + 32];
        float4 ba = fb4[lane], bb = fb4[lane + 32];
        row4[lane]      = make_float4(fmaf(xa.x * rs, ga.x, ba.x), fmaf(xa.y * rs, ga.y, ba.y),
                                      fmaf(xa.z * rs, ga.z, ba.z), fmaf(xa.w * rs, ga.w, ba.w));
        row4[lane + 32] = make_float4(fmaf(xb.x * rs, gb.x, bb.x), fmaf(xb.y * rs, gb.y, bb.y),
                                      fmaf(xb.z * rs, gb.z, bb.z), fmaf(xb.w * rs, gb.w, bb.w));
    }
}

extern "C" void kernel_launch(void* const* d_in, const int* in_sizes, int n_in,
                              void* d_out, int out_size) {
    (void)in_sizes; (void)n_in; (void)out_size;
    const float* feats  = (const float*)d_in[0];
    const float* proj_w = (const float*)d_in[1];
    const float* proj_b = (const float*)d_in[2];
    const float* wq     = (const float*)d_in[3];
    const float* wk     = (const float*)d_in[4];
    const float* wv     = (const float*)d_in[5];
    const float* bq     = (const float*)d_in[6];
    const float* bv     = (const float*)d_in[8];
    const float* wo     = (const float*)d_in[9];
    const float* bo     = (const float*)d_in[10];
    const float* ng     = (const float*)d_in[11];
    const float* nb     = (const float*)d_in[12];
    const float* tfw    = (const float*)d_in[13];
    const float* fg     = (const float*)d_in[14];
    const float* fb     = (const float*)d_in[15];
    float* out = (float*)d_out;

    prep_weights<<<64, 256>>>(proj_w, wq, wk, wv, wo);

    size_t smem = SMEM_HALVES * sizeof(__half);
    cudaFuncSetAttribute(cma_fused, cudaFuncAttributeMaxDynamicSharedMemorySize, (int)smem);
    cma_fused<<<NBLK, THREADS, smem>>>(feats, proj_b, bq, bv, bo,
                                       ng, nb, tfw, fg, fb, out);
}

// round 10
// speedup vs baseline: 2.1112x; 1.0440x over previous
#include <cuda_runtime.h>
#include <cuda_fp16.h>

#define EPSF 1e-5f

namespace {
constexpr int NBLK = 1024;
constexpr int THREADS = 256;
// units = halves unless noted
constexpr int CTXP = 72;            // 144B rows, %32==4 words -> conflict-free ldmatrix
constexpr int WP   = 72;
constexpr int BP   = 72;
constexpr int PC1  = 136;           // spw pitch (k=128)
constexpr int FP   = 72;            // sfeat [c][t] pitch
constexpr int HS   = 64 * 72 + 8;   // bufA head stride (9232 B, 16B-aligned)
constexpr int OP   = 66;            // fp32 O-buffer pitch (floats)

constexpr int OFF_CTX = 0;
constexpr int OFF_W   = OFF_CTX + 256 * CTXP;
constexpr int OFF_W1  = OFF_W + 64 * WP;
constexpr int OFF_A   = OFF_W + 2 * 64 * WP;
constexpr int OFF_B   = OFF_A + 4 * HS;
constexpr int OFF_AB  = OFF_B + 64 * BP;
constexpr int SMEM_HALVES = OFF_AB + 2048;      // 105536 B (2 CTA/SM)
}

// fp16 weight scratch, converted once per launch
__device__ __half g_pw [4 * 64 * 128];   // [k][d][c]
__device__ __half g_wq [4 * 64 * 64];    // [i][e'][t]
__device__ __half g_wkT[4 * 64 * 64];    // [i][t][e]
__device__ __half g_wv [4 * 64 * 64];    // [i][e][t]
__device__ __half g_wo [4 * 64 * 64];    // [i][e'][e]

__global__ void prep_weights(const float* __restrict__ proj_w, const float* __restrict__ wq,
                             const float* __restrict__ wk, const float* __restrict__ wv,
                             const float* __restrict__ wo) {
    int tid = blockIdx.x * blockDim.x + threadIdx.x;
    int stride = gridDim.x * blockDim.x;
    for (int idx = tid; idx < 32768; idx += stride) g_pw[idx] = __float2half_rn(proj_w[idx]);
    for (int idx = tid; idx < 16384; idx += stride) {
        g_wq[idx] = __float2half_rn(wq[idx]);
        g_wv[idx] = __float2half_rn(wv[idx]);
        g_wo[idx] = __float2half_rn(wo[idx]);
        int i = idx >> 12, r = idx & 4095, e = r >> 6, t = r & 63;
        g_wkT[(i << 12) + t * 64 + e] = __float2half_rn(wk[idx]);
    }
}

__device__ __forceinline__ float warp_sum(float v) {
#pragma unroll
    for (int o = 16; o; o >>= 1) v += __shfl_xor_sync(0xffffffffu, v, o);
    return v;
}
__device__ __forceinline__ void mma16(float4& c, unsigned a0, unsigned a1, unsigned a2, unsigned a3,
                                      unsigned b0, unsigned b1) {
    asm volatile("mma.sync.aligned.m16n8k16.row.col.f32.f16.f16.f32 "
                 "{%0,%1,%2,%3}, {%4,%5,%6,%7}, {%8,%9}, {%0,%1,%2,%3};\n"
                 : "+f"(c.x), "+f"(c.y), "+f"(c.z), "+f"(c.w)
                 : "r"(a0), "r"(a1), "r"(a2), "r"(a3), "r"(b0), "r"(b1));
}
__device__ __forceinline__ void sth2(__half* p, float x, float y) {
    *reinterpret_cast<__half2*>(p) = __floats2half2_rn(x, y);
}
__device__ __forceinline__ unsigned sptr(const void* p) {
    return (unsigned)__cvta_generic_to_shared(p);
}
__device__ __forceinline__ void ldsm4(unsigned& r0, unsigned& r1, unsigned& r2, unsigned& r3, unsigned addr) {
    asm volatile("ldmatrix.sync.aligned.m8n8.x4.shared.b16 {%0,%1,%2,%3}, [%4];"
                 : "=r"(r0), "=r"(r1), "=r"(r2), "=r"(r3) : "r"(addr));
}
__device__ __forceinline__ void ldsm4t(unsigned& r0, unsigned& r1, unsigned& r2, unsigned& r3, unsigned addr) {
    asm volatile("ldmatrix.sync.aligned.m8n8.x4.trans.shared.b16 {%0,%1,%2,%3}, [%4];"
                 : "=r"(r0), "=r"(r1), "=r"(r2), "=r"(r3) : "r"(addr));
}
__device__ __forceinline__ __half2 h2u(unsigned u) { return *reinterpret_cast<__half2*>(&u); }

__global__ __launch_bounds__(THREADS, 2)
void cma_fused(const float* __restrict__ feats,
               const float* __restrict__ proj_b, const float* __restrict__ bq,
               const float* __restrict__ bv, const float* __restrict__ bo,
               const float* __restrict__ ng, const float* __restrict__ nb,
               const float* __restrict__ tfw, const float* __restrict__ fg,
               const float* __restrict__ fb, float* __restrict__ out)
{
    extern __shared__ __half smh[];
    __half* sctx  = smh + OFF_CTX;
    __half* slot0 = smh + OFF_W;
    __half* slot1 = smh + OFF_W1;
    __half* bufA  = smh + OFF_A;
    __half* bufB  = smh + OFF_B;
    float*  abuf  = reinterpret_cast<float*>(smh + OFF_AB);
    float*  obuf  = reinterpret_cast<float*>(smh + OFF_A);

    const int b    = blockIdx.x;
    const int tid  = threadIdx.x;
    const int lane = tid & 31;
    const int wid  = tid >> 5;    // 0..7
    const int lg   = lane >> 2;   // 0..7
    const int lt   = lane & 3;    // 0..3
    const int lm   = lane & 15;   // ldmatrix row-within-16
    const int lk8  = (lane >> 4) * 8;
    const int r0s  = (tid >> 4) * 4;
    const int c0s  = (tid & 15) * 4;

    float wgt[4];
    {
        float t0 = __ldg(tfw + 0), t1 = __ldg(tfw + 1), t2 = __ldg(tfw + 2), t3 = __ldg(tfw + 3);
        float tm = fmaxf(fmaxf(t0, t1), fmaxf(t2, t3));
        float e0 = __expf(t0 - tm), e1 = __expf(t1 - tm), e2 = __expf(t2 - tm), e3 = __expf(t3 - tm);
        float inv = 1.f / (e0 + e1 + e2 + e3);
        wgt[0] = e0 * inv; wgt[1] = e1 * inv; wgt[2] = e2 * inv; wgt[3] = e3 * inv;
    }

    // ================= Phase 1: proj -> sctx[(k*64+d)][t] fp16, LDSM frags =================
    {
        __half* spw   = bufA;              // A: [d][c] pitch PC1
        __half* sfeat = bufA + 64 * PC1;   // B: [c][t] pitch FP
        const int m0 = 16 * (wid & 3);
        const int n0 = 32 * (wid >> 2);
        const unsigned aaddr = sptr(spw + (m0 + lm) * PC1 + lk8);
        const unsigned baddr = sptr(sfeat + lm * FP + n0 + lk8);
        for (int k = 0; k < 4; k++) {
            const float4* fgl = reinterpret_cast<const float4*>(feats + (size_t)(k * NBLK + b) * 8192);
#pragma unroll
            for (int idx = tid; idx < 2048; idx += THREADS) {
                int c = idx >> 4, q = idx & 15;
                float4 f = fgl[idx];
                __half2 lo = __floats2half2_rn(f.x, f.y);
                __half2 hi = __floats2half2_rn(f.z, f.w);
                uint2 v;
                v.x = *reinterpret_cast<unsigned*>(&lo);
                v.y = *reinterpret_cast<unsigned*>(&hi);
                *reinterpret_cast<uint2*>(sfeat + c * FP + 4 * q) = v;
            }
            const uint4* pws = reinterpret_cast<const uint4*>(g_pw + k * 8192);
#pragma unroll
            for (int idx = tid; idx < 1024; idx += THREADS) {
                int d = idx >> 4, q = idx & 15;
                reinterpret_cast<uint4*>(spw + d * PC1)[q] = pws[idx];
            }
            __syncthreads();

            float4 acc[4] = {{0,0,0,0},{0,0,0,0},{0,0,0,0},{0,0,0,0}};
#pragma unroll
            for (int k0 = 0; k0 < 128; k0 += 16) {
                unsigned a0, a1, a2, a3, b0, b1, b2, b3, c0, c1, c2, c3;
                ldsm4(a0, a1, a2, a3, aaddr + k0 * 2);
                ldsm4t(b0, b1, b2, b3, baddr + k0 * (FP * 2));
                ldsm4t(c0, c1, c2, c3, baddr + k0 * (FP * 2) + 32);
                mma16(acc[0], a0, a1, a2, a3, b0, b1);
                mma16(acc[1], a0, a1, a2, a3, b2, b3);
                mma16(acc[2], a0, a1, a2, a3, c0, c1);
                mma16(acc[3], a0, a1, a2, a3, c2, c3);
            }
            float pb0 = __ldg(proj_b + k * 64 + m0 + lg);
            float pb1 = __ldg(proj_b + k * 64 + m0 + lg + 8);
            __half* crow0 = sctx + (k * 64 + m0 + lg) * CTXP;
            __half* crow1 = crow0 + 8 * CTXP;
#pragma unroll
            for (int j = 0; j < 4; j++) {
                int col = n0 + 8 * j + 2 * lt;
                sth2(crow0 + col, acc[j].x + pb0, acc[j].y + pb0);
                sth2(crow1 + col, acc[j].z + pb1, acc[j].w + pb1);
            }
            __syncthreads();
        }
    }

    // ================= Phase 2: per-model attention =================
    for (int i = 0; i < 4; i++) {
        {   // stage wq -> slot0, wkT -> slot1
            const uint4* s0 = reinterpret_cast<const uint4*>(g_wq + i * 4096);
            const uint4* s1 = reinterpret_cast<const uint4*>(g_wkT + i * 4096);
#pragma unroll
            for (int idx = tid; idx < 512; idx += THREADS) {
                int e = idx >> 3, q = idx & 7;
                reinterpret_cast<uint4*>(slot0 + e * WP)[q] = s0[idx];
                reinterpret_cast<uint4*>(slot1 + e * WP)[q] = s1[idx];
            }
        }
        __syncthreads();

        // ---- G1: QP[r][e'] = bq + q_in @ wq^T -> bufB (m16n32/warp, all-LDSM) ----
        {
            const int m0 = 16 * (wid & 3);
            const int n0 = 32 * (wid >> 2);
            int rA = m0 + lm;
            int jA = ((rA >> 4) << 6) + ((rA & 15) << 2) + i;
            const unsigned aaddr = sptr(sctx + jA * CTXP + lk8);
            const unsigned baddr0 = sptr(slot0 + (n0 + lm) * WP + lk8);
            const unsigned baddr1 = sptr(slot0 + (n0 + 16 + lm) * WP + lk8);
            float4 acc[4] = {{0,0,0,0},{0,0,0,0},{0,0,0,0},{0,0,0,0}};
#pragma unroll
            for (int k0 = 0; k0 < 64; k0 += 16) {
                unsigned a0, a1, a2, a3, p0, p1, p2, p3, q0, q1, q2, q3;
                ldsm4(a0, a1, a2, a3, aaddr + k0 * 2);
                ldsm4(p0, p1, p2, p3, baddr0 + k0 * 2);
                ldsm4(q0, q1, q2, q3, baddr1 + k0 * 2);
                mma16(acc[0], a0, a1, a2, a3, p0, p2);
                mma16(acc[1], a0, a1, a2, a3, p1, p3);
                mma16(acc[2], a0, a1, a2, a3, q0, q2);
                mma16(acc[3], a0, a1, a2, a3, q1, q3);
            }
            __half* crow0 = bufB + (m0 + lg) * BP;
            __half* crow1 = crow0 + 8 * BP;
#pragma unroll
            for (int j = 0; j < 4; j++) {
                int col = n0 + 8 * j + 2 * lt;
                float b0 = __ldg(bq + i * 64 + col), b1 = __ldg(bq + i * 64 + col + 1);
                sth2(crow0 + col, acc[j].x + b0, acc[j].y + b1);
                sth2(crow1 + col, acc[j].z + b0, acc[j].w + b1);
            }
        }
        __syncthreads();

        // ---- G2: QK[h][r][t] = 0.25 * QP[:,head h] @ wkT -> bufA (all-LDSM, k=16) ----
        {
            const int h  = wid >> 1;
            const int mq = wid & 1;
#pragma unroll
            for (int mt = 0; mt < 2; mt++) {
                const int m0 = 32 * mq + 16 * mt;
                unsigned a0, a1, a2, a3;
                ldsm4(a0, a1, a2, a3, sptr(bufB + (m0 + lm) * BP + 16 * h + lk8));
                float4 acc[8] = {{0,0,0,0},{0,0,0,0},{0,0,0,0},{0,0,0,0},
                                 {0,0,0,0},{0,0,0,0},{0,0,0,0},{0,0,0,0}};
#pragma unroll
                for (int jj = 0; jj < 4; jj++) {
                    unsigned p0, p1, p2, p3;
                    ldsm4(p0, p1, p2, p3, sptr(slot1 + (16 * jj + lm) * WP + 16 * h + lk8));
                    mma16(acc[2 * jj],     a0, a1, a2, a3, p0, p2);
                    mma16(acc[2 * jj + 1], a0, a1, a2, a3, p1, p3);
                }
                __half* crow0 = bufA + h * HS + (m0 + lg) * CTXP;
                __half* crow1 = crow0 + 8 * CTXP;
#pragma unroll
                for (int j = 0; j < 8; j++) {
                    int col = 8 * j + 2 * lt;
                    sth2(crow0 + col, acc[j].x * 0.25f, acc[j].y * 0.25f);
                    sth2(crow1 + col, acc[j].z * 0.25f, acc[j].w * 0.25f);
                }
            }
        }
        __syncthreads();

        // ---- restage wv -> slot0, wo -> slot1; then G3a softmax (uint4 loads, half2 math) ----
        {
            const uint4* s0 = reinterpret_cast<const uint4*>(g_wv + i * 4096);
            const uint4* s1 = reinterpret_cast<const uint4*>(g_wo + i * 4096);
#pragma unroll
            for (int idx = tid; idx < 512; idx += THREADS) {
                int e = idx >> 3, q = idx & 7;
                reinterpret_cast<uint4*>(slot0 + e * WP)[q] = s0[idx];
                reinterpret_cast<uint4*>(slot1 + e * WP)[q] = s1[idx];
            }
        }
#pragma unroll
        for (int p = 0; p < 4; p++) {
            int r   = wid * 8 + p * 2 + (lane >> 4);
            int sub = lane & 15;
            int h   = sub >> 2, kp = sub & 3;
            int j   = ((r >> 4) << 6) + ((r & 15) << 2) + kp;
            const uint4* qr4 = reinterpret_cast<const uint4*>(bufA + h * HS + r * CTXP);
            const uint4* cr4 = reinterpret_cast<const uint4*>(sctx + j * CTXP);
            __half2 ac0 = __float2half2_rn(0.f), ac1 = ac0;
#pragma unroll
            for (int t0 = 0; t0 < 8; t0++) {
                uint4 q = qr4[t0], c = cr4[t0];
                ac0 = __hfma2(h2u(q.x), h2u(c.x), ac0);
                ac1 = __hfma2(h2u(q.y), h2u(c.y), ac1);
                ac0 = __hfma2(h2u(q.z), h2u(c.z), ac0);
                ac1 = __hfma2(h2u(q.w), h2u(c.w), ac1);
            }
            float2 f0 = __half22float2(ac0), f1 = __half22float2(ac1);
            float s = (f0.x + f0.y) + (f1.x + f1.y);
            float m = fmaxf(s, __shfl_xor_sync(0xffffffffu, s, 1));
            m = fmaxf(m, __shfl_xor_sync(0xffffffffu, m, 2));
            float pe  = __expf(s - m);
            float den = pe + __shfl_xor_sync(0xffffffffu, pe, 1);
            den += __shfl_xor_sync(0xffffffffu, den, 2);
            abuf[r * 16 + sub] = pe / den;
        }
        __syncthreads();

        // ---- G3b: AGG[h][r][t] = sum_kp a * ctx (ctx hoisted across heads, 64-bit ops) ----
        {
#pragma unroll
            for (int rr = 0; rr < 4; rr++) {
                int r  = r0s + rr;
                int jb = ((r >> 4) << 6) + ((r & 15) << 2);
                // ctx rows are head-independent: load 4 kp rows once
                __half2 cx[4][2];
#pragma unroll
                for (int kp = 0; kp < 4; kp++) {
                    uint2 cv = *reinterpret_cast<const uint2*>(sctx + (jb + kp) * CTXP + c0s);
                    cx[kp][0] = h2u(cv.x);
                    cx[kp][1] = h2u(cv.y);
                }
                const float4* arow = reinterpret_cast<const float4*>(abuf + r * 16);
#pragma unroll
                for (int h = 0; h < 4; h++) {
                    float4 a4 = arow[h];
                    __half2 acc0 = __float2half2_rn(0.f), acc1 = acc0;
#pragma unroll
                    for (int kp = 0; kp < 4; kp++) {
                        __half2 ah = __float2half2_rn((&a4.x)[kp]);
                        acc0 = __hfma2(ah, cx[kp][0], acc0);
                        acc1 = __hfma2(ah, cx[kp][1], acc1);
                    }
                    uint2 ov;
                    ov.x = *reinterpret_cast<unsigned*>(&acc0);
                    ov.y = *reinterpret_cast<unsigned*>(&acc1);
                    *reinterpret_cast<uint2*>(bufA + h * HS + r * CTXP + c0s) = ov;
                }
            }
        }
        __syncthreads();

        // ---- G4: OA[r][e] = bv + AGG[h(e)] @ wv^T -> bufB (all-LDSM) ----
        {
            const int h  = wid >> 1;
            const int mq = wid & 1;
            const unsigned baddr = sptr(slot0 + (16 * h + lm) * WP + lk8);
#pragma unroll
            for (int mt = 0; mt < 2; mt++) {
                const int m0 = 32 * mq + 16 * mt;
                const unsigned aaddr = sptr(bufA + h * HS + (m0 + lm) * CTXP + lk8);
                float4 acc[2] = {{0,0,0,0},{0,0,0,0}};
#pragma unroll
                for (int k0 = 0; k0 < 64; k0 += 16) {
                    unsigned a0, a1, a2, a3, p0, p1, p2, p3;
                    ldsm4(a0, a1, a2, a3, aaddr + k0 * 2);
                    ldsm4(p0, p1, p2, p3, baddr + k0 * 2);
                    mma16(acc[0], a0, a1, a2, a3, p0, p2);
                    mma16(acc[1], a0, a1, a2, a3, p1, p3);
                }
                __half* crow0 = bufB + (m0 + lg) * BP;
                __half* crow1 = crow0 + 8 * BP;
#pragma unroll
                for (int j = 0; j < 2; j++) {
                    int col = 16 * h + 8 * j + 2 * lt;
                    float b0 = __ldg(bv + i * 64 + col), b1 = __ldg(bv + i * 64 + col + 1);
                    sth2(crow0 + col, acc[j].x + b0, acc[j].y + b1);
                    sth2(crow1 + col, acc[j].z + b0, acc[j].w + b1);
                }
            }
        }
        __syncthreads();

        // ---- G5: O[r][e'] = bo + OA @ wo^T -> obuf fp32 (all-LDSM) ----
        {
            const int m0 = 16 * (wid & 3);
            const int n0 = 32 * (wid >> 2);
            const unsigned aaddr  = sptr(bufB + (m0 + lm) * BP + lk8);
            const unsigned baddr0 = sptr(slot1 + (n0 + lm) * WP + lk8);
            const unsigned baddr1 = sptr(slot1 + (n0 + 16 + lm) * WP + lk8);
            float4 acc[4] = {{0,0,0,0},{0,0,0,0},{0,0,0,0},{0,0,0,0}};
#pragma unroll
            for (int k0 = 0; k0 < 64; k0 += 16) {
                unsigned a0, a1, a2, a3, p0, p1, p2, p3, q0, q1, q2, q3;
                ldsm4(a0, a1, a2, a3, aaddr + k0 * 2);
                ldsm4(p0, p1, p2, p3, baddr0 + k0 * 2);
                ldsm4(q0, q1, q2, q3, baddr1 + k0 * 2);
                mma16(acc[0], a0, a1, a2, a3, p0, p2);
                mma16(acc[1], a0, a1, a2, a3, p1, p3);
                mma16(acc[2], a0, a1, a2, a3, q0, q2);
                mma16(acc[3], a0, a1, a2, a3, q1, q3);
            }
            float* crow0 = obuf + (m0 + lg) * OP;
            float* crow1 = crow0 + 8 * OP;
#pragma unroll
            for (int j = 0; j < 4; j++) {
                int col = n0 + 8 * j + 2 * lt;
                float b0 = __ldg(bo + i * 64 + col), b1 = __ldg(bo + i * 64 + col + 1);
                crow0[col]     = acc[j].x + b0;
                crow0[col + 1] = acc[j].y + b1;
                crow1[col]     = acc[j].z + b0;
                crow1[col + 1] = acc[j].w + b1;
            }
        }
        __syncthreads();

        // ---- LN over 64 (+residual q_in), scale by wgt[i], stage into out ----
#pragma unroll
        for (int p = 0; p < 8; p++) {
            int r   = wid * 8 + p;
            int jqr = ((r >> 4) << 6) + ((r & 15) << 2) + i;
            float x0 = obuf[r * OP + lane]      + __half2float(sctx[jqr * CTXP + lane]);
            float x1 = obuf[r * OP + lane + 32] + __half2float(sctx[jqr * CTXP + lane + 32]);
            float mean = warp_sum(x0 + x1) * (1.f / 64.f);
            float d0 = x0 - mean, d1 = x1 - mean;
            float var = warp_sum(d0 * d0 + d1 * d1) * (1.f / 64.f);
            float rs = rsqrtf(var + EPSF);
            float* dst = out + ((size_t)b * 16384 + r * 256 + i * 64);
            dst[lane]      = (d0 * rs * __ldg(ng + i * 64 + lane)      + __ldg(nb + i * 64 + lane))      * wgt[i];
            dst[lane + 32] = (d1 * rs * __ldg(ng + i * 64 + lane + 32) + __ldg(nb + i * 64 + lane + 32)) * wgt[i];
        }
        __syncthreads();
    }

    // ================= Phase 3: final LN over 256, in-place on out =================
    const float4* fg4 = reinterpret_cast<const float4*>(fg);
    const float4* fb4 = reinterpret_cast<const float4*>(fb);
#pragma unroll
    for (int p = 0; p < 8; p++) {
        int r = wid * 8 + p;
        float4* row4 = reinterpret_cast<float4*>(out + (size_t)b * 16384 + r * 256);
        float4 xa = row4[lane], xb = row4[lane + 32];
        float s = xa.x + xa.y + xa.z + xa.w + xb.x + xb.y + xb.z + xb.w;
        float mean = warp_sum(s) * (1.f / 256.f);
        xa.x -= mean; xa.y -= mean; xa.z -= mean; xa.w -= mean;
        xb.x -= mean; xb.y -= mean; xb.z -= mean; xb.w -= mean;
        float v = xa.x*xa.x + xa.y*xa.y + xa.z*xa.z + xa.w*xa.w
                + xb.x*xb.x + xb.y*xb.y + xb.z*xb.z + xb.w*xb.w;
        float var = warp_sum(v) * (1.f / 256.f);
        float rs = rsqrtf(var + EPSF);
        float4 ga = fg4[lane], gb = fg4[lane + 32];
        float4 ba = fb4[lane], bb = fb4[lane + 32];
        row4[lane]      = make_float4(fmaf(xa.x * rs, ga.x, ba.x), fmaf(xa.y * rs, ga.y, ba.y),
                                      fmaf(xa.z * rs, ga.z, ba.z), fmaf(xa.w * rs, ga.w, ba.w));
        row4[lane + 32] = make_float4(fmaf(xb.x * rs, gb.x, bb.x), fmaf(xb.y * rs, gb.y, bb.y),
                                      fmaf(xb.z * rs, gb.z, bb.z), fmaf(xb.w * rs, gb.w, bb.w));
    }
}

extern "C" void kernel_launch(void* const* d_in, const int* in_sizes, int n_in,
                              void* d_out, int out_size) {
    (void)in_sizes; (void)n_in; (void)out_size;
    const float* feats  = (const float*)d_in[0];
    const float* proj_w = (const float*)d_in[1];
    const float* proj_b = (const float*)d_in[2];
    const float* wq     = (const float*)d_in[3];
    const float* wk     = (const float*)d_in[4];
    const float* wv     = (const float*)d_in[5];
    const float* bq     = (const float*)d_in[6];
    const float* bv     = (const float*)d_in[8];
    const float* wo     = (const float*)d_in[9];
    const float* bo     = (const float*)d_in[10];
    const float* ng     = (const float*)d_in[11];
    const float* nb     = (const float*)d_in[12];
    const float* tfw    = (const float*)d_in[13];
    const float* fg     = (const float*)d_in[14];
    const float* fb     = (const float*)d_in[15];
    float* out = (float*)d_out;

    prep_weights<<<64, 256>>>(proj_w, wq, wk, wv, wo);

    size_t smem = SMEM_HALVES * sizeof(__half);
    cudaFuncSetAttribute(cma_fused, cudaFuncAttributeMaxDynamicSharedMemorySize, (int)smem);
    cma_fused<<<NBLK, THREADS, smem>>>(feats, proj_b, bq, bv, bo,
                                       ng, nb, tfw, fg, fb, out);
}